// round 2
// baseline (speedup 1.0000x reference)
#include <cuda_runtime.h>
#include <cstddef>

// ---------------- problem constants ----------------
#define BB 8
#define NN 256
#define DD_ 768          // node dim
#define EW 64            // edge width
#define HH 32            // heads
#define DDOT 24          // dot dim
#define ROWS (BB*NN)     // 2048
#define SCALE_Q 0.20412414523193154f   // 24^-0.5
#define FULLMASK 0xffffffffu

// ---------------- scratch (device globals; no allocation) ----------------
__device__ float g_hln [ROWS*DD_];
__device__ float g_qkv [ROWS*3*DD_];
__device__ float g_vatt[ROWS*DD_];
__device__ float g_hmid[ROWS*DD_];
__device__ float g_hln2[ROWS*DD_];
__device__ float g_t   [ROWS*DD_];

// ---------------- helpers ----------------
__device__ __forceinline__ float warpSum(float v){
#pragma unroll
    for (int o = 16; o; o >>= 1) v += __shfl_xor_sync(FULLMASK, v, o);
    return v;
}

__device__ __forceinline__ float gelu_tanh(float x){
    // jax.nn.gelu default (approximate=True)
    float y = 0.7978845608028654f * (x + 0.044715f * x * x * x);
    y = fminf(fmaxf(y, -30.f), 30.f);
    float t = __expf(2.f * y);
    float th = (t - 1.f) / (t + 1.f);
    return 0.5f * x * (1.f + th);
}

__device__ __forceinline__ float sigmoidf_(float x){
    return 1.f / (1.f + __expf(-x));
}

// ---------------- LayerNorm over 768, one CTA per row ----------------
__global__ __launch_bounds__(256) void ln768_kernel(
    const float* __restrict__ x, const float* __restrict__ g,
    const float* __restrict__ b, float* __restrict__ y)
{
    int row = blockIdx.x;
    int tid = threadIdx.x;
    const float* xr = x + (size_t)row * DD_;
    float*       yr = y + (size_t)row * DD_;

    float v0 = xr[tid], v1 = xr[tid+256], v2 = xr[tid+512];
    __shared__ float red[8];

    float s = warpSum(v0 + v1 + v2);
    if ((tid & 31) == 0) red[tid >> 5] = s;
    __syncthreads();
    float tot = 0.f;
#pragma unroll
    for (int i = 0; i < 8; i++) tot += red[i];
    __syncthreads();
    float mean = tot * (1.f/768.f);
    float d0 = v0-mean, d1 = v1-mean, d2 = v2-mean;
    float q = warpSum(d0*d0 + d1*d1 + d2*d2);
    if ((tid & 31) == 0) red[tid >> 5] = q;
    __syncthreads();
    float vt = 0.f;
#pragma unroll
    for (int i = 0; i < 8; i++) vt += red[i];
    float rstd = rsqrtf(vt * (1.f/768.f) + 1e-5f);
    yr[tid]     = d0*rstd*g[tid]     + b[tid];
    yr[tid+256] = d1*rstd*g[tid+256] + b[tid+256];
    yr[tid+512] = d2*rstd*g[tid+512] + b[tid+512];
}

// ---------------- fp32 GEMM  C = epi(A@B + bias) [+ R] ----------------
// A[M,K] row-major, B[K,N] row-major. BM=128, BN=64, BK=16, 256 threads, 8x4/thread.
template<int EPI>  // 0 none, 1 gelu
__global__ __launch_bounds__(256) void gemm_epi(
    const float* __restrict__ A, const float* __restrict__ Bm,
    const float* __restrict__ bias, const float* __restrict__ R,
    float* __restrict__ C, int M, int N, int K)
{
    __shared__ float sA[16][132];
    __shared__ float sB[16][64];

    int m0 = blockIdx.y * 128;
    int n0 = blockIdx.x * 64;
    int tid = threadIdx.x;
    int ty = tid >> 4;       // 0..15 -> rows ty*8..+7
    int tx = tid & 15;       // 0..15 -> cols tx*4..+3

    float acc[8][4];
#pragma unroll
    for (int i = 0; i < 8; i++)
#pragma unroll
        for (int j = 0; j < 4; j++) acc[i][j] = 0.f;

    for (int k0 = 0; k0 < K; k0 += 16){
#pragma unroll
        for (int x = 0; x < 8; x++){
            int idx = tid + x*256;
            int m = idx >> 4, kk = idx & 15;
            sA[kk][m] = A[(size_t)(m0+m)*K + k0 + kk];
        }
#pragma unroll
        for (int x = 0; x < 4; x++){
            int idx = tid + x*256;
            int kk = idx >> 6, n = idx & 63;
            sB[kk][n] = Bm[(size_t)(k0+kk)*N + n0 + n];
        }
        __syncthreads();
#pragma unroll
        for (int kk = 0; kk < 16; kk++){
            float4 a0 = *(const float4*)&sA[kk][ty*8];
            float4 a1 = *(const float4*)&sA[kk][ty*8+4];
            float4 b0 = *(const float4*)&sB[kk][tx*4];
            float a[8] = {a0.x,a0.y,a0.z,a0.w,a1.x,a1.y,a1.z,a1.w};
            float bv[4] = {b0.x,b0.y,b0.z,b0.w};
#pragma unroll
            for (int i = 0; i < 8; i++)
#pragma unroll
                for (int j = 0; j < 4; j++) acc[i][j] += a[i]*bv[j];
        }
        __syncthreads();
    }
#pragma unroll
    for (int i = 0; i < 8; i++){
        int m = m0 + ty*8 + i;
#pragma unroll
        for (int j = 0; j < 4; j++){
            int n = n0 + tx*4 + j;
            float v = acc[i][j] + bias[n];
            if (EPI == 1) v = gelu_tanh(v);
            if (R) v += R[(size_t)m*N + n];
            C[(size_t)m*N + n] = v;
        }
    }
}

// ---------------- fused edge kernel: one CTA per (b,l) ----------------
// Pass 1 (4 edges / warp-iter): LN(e) -> E,G ; H_hat = QK^T + E ; gates ;
//          e_att = H_hat@W_oe ; edge residual + edge FFN -> e_out.
// Pass 2: softmax over m (SMEM-resident H_hat), A = softmax*gates,
//          V_att = (A @ V) * log1p(sum gates) -> g_vatt.
#define EDGE_SMEM_FLOATS 36864
__global__ __launch_bounds__(256) void edge_attn_kernel(
    const float* __restrict__ e_in, const float* __restrict__ mask,
    const float* __restrict__ qkv,
    const float* __restrict__ W_eg, const float* __restrict__ b_eg,
    const float* __restrict__ W_oe, const float* __restrict__ b_oe,
    const float* __restrict__ eln_g, const float* __restrict__ eln_b,
    const float* __restrict__ ffn_g, const float* __restrict__ ffn_b,
    const float* __restrict__ eW1, const float* __restrict__ eb1,
    const float* __restrict__ eW2, const float* __restrict__ eb2,
    float* __restrict__ e_out, float* __restrict__ vatt)
{
    extern __shared__ float smem[];
    float* sQ    = smem;               // 768
    float* sWeg  = sQ    + 768;        // 4096
    float* sWoe  = sWeg  + 4096;       // 2048
    float* sEW1  = sWoe  + 2048;       // 4096
    float* sEW2  = sEW1  + 4096;       // 4096
    float* sPar  = sEW2  + 4096;       // 512
    float* sHhat = sPar  + 512;        // 256*32
    float* sGate = sHhat + 8192;       // 256*32
    float* sMask = sGate + 8192;       // 256
    float* sVa   = sMask + 256;        // 8 * 64*4
    float* sVb   = sVa   + 2048;       // 8 * 64*4
    float* sRed  = sVb   + 2048;       // 256
    float* sRed2 = sRed  + 256;        // 256

    int tid  = threadIdx.x;
    int w    = tid >> 5;
    int lane = tid & 31;
    int row  = blockIdx.x;            // b*256 + l
    int b    = row >> 8;

    for (int i = tid; i < 768; i += 256) sQ[i] = qkv[(size_t)row*2304 + i] * SCALE_Q;
    for (int i = tid; i < 4096; i += 256){ sWeg[i]=W_eg[i]; sEW1[i]=eW1[i]; sEW2[i]=eW2[i]; }
    for (int i = tid; i < 2048; i += 256) sWoe[i]=W_oe[i];
    if (tid < 64){
        sPar[tid]     = b_eg[tid];
        sPar[64+tid]  = b_oe[tid];
        sPar[128+tid] = eb1[tid];
        sPar[192+tid] = eb2[tid];
        sPar[256+tid] = eln_g[tid];
        sPar[320+tid] = eln_b[tid];
        sPar[384+tid] = ffn_g[tid];
        sPar[448+tid] = ffn_b[tid];
    }
    __syncthreads();
    const float* beg = sPar;       const float* boe = sPar+64;
    const float* sb1 = sPar+128;   const float* sb2 = sPar+192;
    const float* lg  = sPar+256;   const float* lb  = sPar+320;
    const float* fg  = sPar+384;   const float* fb  = sPar+448;
    float* myVa = sVa + w*256;
    float* myVb = sVb + w*256;

    // ---------- pass 1 ----------
    for (int gidx = 0; gidx < 8; ++gidx){
        int mb = w*32 + gidx*4;
        float e0[4], e1[4], l0[4], l1[4];
#pragma unroll
        for (int mm = 0; mm < 4; mm++){
            const float* er = e_in + ((size_t)row*256 + mb+mm)*64;
            e0[mm] = er[lane]; e1[mm] = er[lane+32];
        }
#pragma unroll
        for (int mm = 0; mm < 4; mm++){
            float mean = warpSum(e0[mm]+e1[mm]) * (1.f/64.f);
            float d0 = e0[mm]-mean, d1 = e1[mm]-mean;
            float var = warpSum(d0*d0 + d1*d1) * (1.f/64.f);
            float rs = rsqrtf(var + 1e-5f);
            l0[mm] = d0*rs*lg[lane]    + lb[lane];
            l1[mm] = d1*rs*lg[lane+32] + lb[lane+32];
        }
        __syncwarp();
#pragma unroll
        for (int mm = 0; mm < 4; mm++){ myVa[lane*4+mm]=l0[mm]; myVa[(lane+32)*4+mm]=l1[mm]; }
        __syncwarp();

        // eg = e_ln @ W_eg + b_eg ; E = cols[0:32], G = cols[32:64]
        float E[4], G[4];
#pragma unroll
        for (int mm = 0; mm < 4; mm++){ E[mm]=beg[lane]; G[mm]=beg[lane+32]; }
#pragma unroll 8
        for (int i = 0; i < 64; i++){
            float4 x = *(const float4*)&myVa[i*4];
            float w0 = sWeg[i*64+lane], w1 = sWeg[i*64+32+lane];
            E[0]+=x.x*w0; E[1]+=x.y*w0; E[2]+=x.z*w0; E[3]+=x.w*w0;
            G[0]+=x.x*w1; G[1]+=x.y*w1; G[2]+=x.z*w1; G[3]+=x.w*w1;
        }

        // H_hat = Q . K  (per head = lane), + E
        float hq[4];
#pragma unroll
        for (int mm = 0; mm < 4; mm++){
            const float* kr = qkv + (size_t)(b*256 + mb+mm)*2304 + 768;
            float a = E[mm];
#pragma unroll
            for (int d = 0; d < 24; d++) a += sQ[d*32+lane] * kr[d*32+lane];
            hq[mm] = a;
        }
#pragma unroll
        for (int mm = 0; mm < 4; mm++){
            float mk = __ldg(&mask[(size_t)row*256 + mb+mm]);
            float gt = sigmoidf_(G[mm] + mk);
            sHhat[(mb+mm)*32 + lane] = hq[mm];
            sGate[(mb+mm)*32 + lane] = gt;
            if (lane == 0) sMask[mb+mm] = mk;
        }

        // e_att = H_hat @ W_oe + b_oe  (broadcast hq across lanes via shfl)
        float eo0[4], eo1[4];
#pragma unroll
        for (int mm = 0; mm < 4; mm++){ eo0[mm]=boe[lane]; eo1[mm]=boe[lane+32]; }
#pragma unroll 8
        for (int j = 0; j < 32; j++){
            float w0 = sWoe[j*64+lane], w1 = sWoe[j*64+32+lane];
#pragma unroll
            for (int mm = 0; mm < 4; mm++){
                float hj = __shfl_sync(FULLMASK, hq[mm], j);
                eo0[mm] += hj*w0; eo1[mm] += hj*w1;
            }
        }

        // edge residual + FFN
        float r0[4], r1[4], f0[4], f1[4];
#pragma unroll
        for (int mm = 0; mm < 4; mm++){ r0[mm]=e0[mm]+eo0[mm]; r1[mm]=e1[mm]+eo1[mm]; }
#pragma unroll
        for (int mm = 0; mm < 4; mm++){
            float mean = warpSum(r0[mm]+r1[mm]) * (1.f/64.f);
            float d0 = r0[mm]-mean, d1 = r1[mm]-mean;
            float var = warpSum(d0*d0 + d1*d1) * (1.f/64.f);
            float rs = rsqrtf(var + 1e-5f);
            f0[mm] = d0*rs*fg[lane]    + fb[lane];
            f1[mm] = d1*rs*fg[lane+32] + fb[lane+32];
        }
        __syncwarp();
#pragma unroll
        for (int mm = 0; mm < 4; mm++){ myVa[lane*4+mm]=f0[mm]; myVa[(lane+32)*4+mm]=f1[mm]; }
        __syncwarp();

        float t0[4], t1[4];
#pragma unroll
        for (int mm = 0; mm < 4; mm++){ t0[mm]=sb1[lane]; t1[mm]=sb1[lane+32]; }
#pragma unroll 8
        for (int i = 0; i < 64; i++){
            float4 x = *(const float4*)&myVa[i*4];
            float w0 = sEW1[i*64+lane], w1 = sEW1[i*64+32+lane];
            t0[0]+=x.x*w0; t0[1]+=x.y*w0; t0[2]+=x.z*w0; t0[3]+=x.w*w0;
            t1[0]+=x.x*w1; t1[1]+=x.y*w1; t1[2]+=x.z*w1; t1[3]+=x.w*w1;
        }
#pragma unroll
        for (int mm = 0; mm < 4; mm++){ t0[mm]=gelu_tanh(t0[mm]); t1[mm]=gelu_tanh(t1[mm]); }
        __syncwarp();
#pragma unroll
        for (int mm = 0; mm < 4; mm++){ myVb[lane*4+mm]=t0[mm]; myVb[(lane+32)*4+mm]=t1[mm]; }
        __syncwarp();

        float o0[4], o1[4];
#pragma unroll
        for (int mm = 0; mm < 4; mm++){ o0[mm]=sb2[lane]; o1[mm]=sb2[lane+32]; }
#pragma unroll 8
        for (int i = 0; i < 64; i++){
            float4 x = *(const float4*)&myVb[i*4];
            float w0 = sEW2[i*64+lane], w1 = sEW2[i*64+32+lane];
            o0[0]+=x.x*w0; o0[1]+=x.y*w0; o0[2]+=x.z*w0; o0[3]+=x.w*w0;
            o1[0]+=x.x*w1; o1[1]+=x.y*w1; o1[2]+=x.z*w1; o1[3]+=x.w*w1;
        }
#pragma unroll
        for (int mm = 0; mm < 4; mm++){
            float* eo = e_out + ((size_t)row*256 + mb+mm)*64;
            eo[lane]    = r0[mm] + o0[mm];
            eo[lane+32] = r1[mm] + o1[mm];
        }
    }
    __syncthreads();

    // ---------- pass 2: softmax over m + AV ----------
    float pm = -3.4e38f;
    for (int mm = 0; mm < 32; mm++){
        int m = w*32 + mm;
        pm = fmaxf(pm, sHhat[m*32+lane] + sMask[m]);
    }
    sRed[w*32+lane] = pm;
    __syncthreads();
    float mx = sRed[lane];
#pragma unroll
    for (int i = 1; i < 8; i++) mx = fmaxf(mx, sRed[i*32+lane]);
    __syncthreads();

    float ps = 0.f, pg = 0.f;
    for (int mm = 0; mm < 32; mm++){
        int m = w*32 + mm;
        float a = __expf(sHhat[m*32+lane] + sMask[m] - mx);
        sHhat[m*32+lane] = a;
        ps += a;
        pg += sGate[m*32+lane];
    }
    sRed[w*32+lane] = ps; sRed2[w*32+lane] = pg;
    __syncthreads();
    float s = 0.f, gs = 0.f;
#pragma unroll
    for (int i = 0; i < 8; i++){ s += sRed[i*32+lane]; gs += sRed2[i*32+lane]; }
    float inv = 1.f / s;
    float deg = log1pf(gs);

    for (int mm = 0; mm < 32; mm++){
        int m = w*32 + mm;
        sHhat[m*32+lane] = sHhat[m*32+lane] * inv * sGate[m*32+lane];
    }
    __syncthreads();

    const float* Vb = qkv + (size_t)b*256*2304 + 1536;
    float a0 = 0.f, a1 = 0.f, a2 = 0.f;
    int d0 = w, d1 = w+8, d2 = w+16;
#pragma unroll 4
    for (int m = 0; m < 256; m++){
        float a = sHhat[m*32 + lane];
        const float* vr = Vb + (size_t)m*2304;
        a0 += a * vr[d0*32 + lane];
        a1 += a * vr[d1*32 + lane];
        a2 += a * vr[d2*32 + lane];
    }
    float* vo = vatt + (size_t)row*768;
    vo[d0*32+lane] = a0*deg;
    vo[d1*32+lane] = a1*deg;
    vo[d2*32+lane] = a2*deg;
}

// ---------------- host ----------------
extern "C" void kernel_launch(void* const* d_in, const int* in_sizes, int n_in,
                              void* d_out, int out_size)
{
    const float* h_in   = (const float*)d_in[0];
    const float* e_in   = (const float*)d_in[1];
    const float* mask   = (const float*)d_in[2];
    const float* ln_h_g = (const float*)d_in[3];
    const float* ln_h_b = (const float*)d_in[4];
    const float* ln_e_g = (const float*)d_in[5];
    const float* ln_e_b = (const float*)d_in[6];
    const float* W_qkv  = (const float*)d_in[7];
    const float* b_qkv  = (const float*)d_in[8];
    const float* W_eg   = (const float*)d_in[9];
    const float* b_eg   = (const float*)d_in[10];
    const float* W_oh   = (const float*)d_in[11];
    const float* b_oh   = (const float*)d_in[12];
    const float* W_oe   = (const float*)d_in[13];
    const float* b_oe   = (const float*)d_in[14];
    const float* nffn_g = (const float*)d_in[15];
    const float* nffn_b = (const float*)d_in[16];
    const float* nW1    = (const float*)d_in[17];
    const float* nb1    = (const float*)d_in[18];
    const float* nW2    = (const float*)d_in[19];
    const float* nb2    = (const float*)d_in[20];
    const float* effn_g = (const float*)d_in[21];
    const float* effn_b = (const float*)d_in[22];
    const float* eW1    = (const float*)d_in[23];
    const float* eb1    = (const float*)d_in[24];
    const float* eW2    = (const float*)d_in[25];
    const float* eb2    = (const float*)d_in[26];

    float* out_h = (float*)d_out;
    float* out_e = out_h + (size_t)ROWS * DD_;

    float *hln, *qkv, *vatt, *hmid, *hln2, *tbuf;
    cudaGetSymbolAddress((void**)&hln,  g_hln);
    cudaGetSymbolAddress((void**)&qkv,  g_qkv);
    cudaGetSymbolAddress((void**)&vatt, g_vatt);
    cudaGetSymbolAddress((void**)&hmid, g_hmid);
    cudaGetSymbolAddress((void**)&hln2, g_hln2);
    cudaGetSymbolAddress((void**)&tbuf, g_t);

    cudaFuncSetAttribute(edge_attn_kernel,
                         cudaFuncAttributeMaxDynamicSharedMemorySize,
                         EDGE_SMEM_FLOATS * 4);

    // 1) h layernorm
    ln768_kernel<<<ROWS, 256>>>(h_in, ln_h_g, ln_h_b, hln);

    // 2) QKV = h_ln @ W_qkv + b_qkv   [2048 x 2304]
    gemm_epi<0><<<dim3(2304/64, ROWS/128), 256>>>(hln, W_qkv, b_qkv, nullptr, qkv,
                                                  ROWS, 2304, DD_);

    // 3) fused edge attention + edge FFN (+ V_att)
    edge_attn_kernel<<<ROWS, 256, EDGE_SMEM_FLOATS * 4>>>(
        e_in, mask, qkv,
        W_eg, b_eg, W_oe, b_oe,
        ln_e_g, ln_e_b, effn_g, effn_b,
        eW1, eb1, eW2, eb2,
        out_e, vatt);

    // 4) h_mid = h + V_att @ W_oh + b_oh
    gemm_epi<0><<<dim3(DD_/64, ROWS/128), 256>>>(vatt, W_oh, b_oh, h_in, hmid,
                                                 ROWS, DD_, DD_);

    // 5) node FFN
    ln768_kernel<<<ROWS, 256>>>(hmid, nffn_g, nffn_b, hln2);
    gemm_epi<1><<<dim3(DD_/64, ROWS/128), 256>>>(hln2, nW1, nb1, nullptr, tbuf,
                                                 ROWS, DD_, DD_);
    gemm_epi<0><<<dim3(DD_/64, ROWS/128), 256>>>(tbuf, nW2, nb2, hmid, out_h,
                                                 ROWS, DD_, DD_);
}

// round 3
// speedup vs baseline: 1.1526x; 1.1526x over previous
#include <cuda_runtime.h>
#include <cstddef>

// ---------------- problem constants ----------------
#define BB 8
#define NN 256
#define DD_ 768
#define ROWS (BB*NN)     // 2048
#define SCALE_Q 0.20412414523193154f   // 24^-0.5
#define FULLMASK 0xffffffffu

// ---------------- scratch (device globals; no allocation) ----------------
__device__ float g_hln [ROWS*DD_];
__device__ float g_qt  [8*32*256*24];
__device__ float g_kt  [8*32*256*24];
__device__ float g_vt  [8*32*256*24];
__device__ float g_qk  [8*32*256*256];
__device__ float g_a   [8*32*256*256];
__device__ float g_vatt[ROWS*DD_];
__device__ float g_hmid[ROWS*DD_];
__device__ float g_hln2[ROWS*DD_];
__device__ float g_t   [ROWS*DD_];

// ---------------- helpers ----------------
__device__ __forceinline__ float warpSum(float v){
#pragma unroll
    for (int o = 16; o; o >>= 1) v += __shfl_xor_sync(FULLMASK, v, o);
    return v;
}
__device__ __forceinline__ float warpMax(float v){
#pragma unroll
    for (int o = 16; o; o >>= 1) v = fmaxf(v, __shfl_xor_sync(FULLMASK, v, o));
    return v;
}
__device__ __forceinline__ float gelu_tanh(float x){
    float y = 0.7978845608028654f * (x + 0.044715f * x * x * x);
    y = fminf(fmaxf(y, -30.f), 30.f);
    float t = __expf(2.f * y);
    float th = (t - 1.f) / (t + 1.f);
    return 0.5f * x * (1.f + th);
}
__device__ __forceinline__ float sigmoidf_(float x){
    return 1.f / (1.f + __expf(-x));
}

// ---------------- LayerNorm over 768 ----------------
__global__ __launch_bounds__(256) void ln768_kernel(
    const float* __restrict__ x, const float* __restrict__ g,
    const float* __restrict__ b, float* __restrict__ y)
{
    int row = blockIdx.x;
    int tid = threadIdx.x;
    const float* xr = x + (size_t)row * DD_;
    float*       yr = y + (size_t)row * DD_;
    float v0 = xr[tid], v1 = xr[tid+256], v2 = xr[tid+512];
    __shared__ float red[8];
    float s = warpSum(v0 + v1 + v2);
    if ((tid & 31) == 0) red[tid >> 5] = s;
    __syncthreads();
    float tot = 0.f;
#pragma unroll
    for (int i = 0; i < 8; i++) tot += red[i];
    __syncthreads();
    float mean = tot * (1.f/768.f);
    float d0 = v0-mean, d1 = v1-mean, d2 = v2-mean;
    float q = warpSum(d0*d0 + d1*d1 + d2*d2);
    if ((tid & 31) == 0) red[tid >> 5] = q;
    __syncthreads();
    float vt = 0.f;
#pragma unroll
    for (int i = 0; i < 8; i++) vt += red[i];
    float rstd = rsqrtf(vt * (1.f/768.f) + 1e-5f);
    yr[tid]     = d0*rstd*g[tid]     + b[tid];
    yr[tid+256] = d1*rstd*g[tid+256] + b[tid+256];
    yr[tid+512] = d2*rstd*g[tid+512] + b[tid+512];
}

// ---------------- generic fp32 GEMM C = epi(A@B + bias) [+ R] ----------------
template<int EPI>  // 0 none, 1 gelu
__global__ __launch_bounds__(256) void gemm_epi(
    const float* __restrict__ A, const float* __restrict__ Bm,
    const float* __restrict__ bias, const float* __restrict__ R,
    float* __restrict__ C, int M, int N, int K)
{
    __shared__ float sA[16][132];
    __shared__ float sB[16][64];
    int m0 = blockIdx.y * 128;
    int n0 = blockIdx.x * 64;
    int tid = threadIdx.x;
    int ty = tid >> 4;
    int tx = tid & 15;
    float acc[8][4];
#pragma unroll
    for (int i = 0; i < 8; i++)
#pragma unroll
        for (int j = 0; j < 4; j++) acc[i][j] = 0.f;
    for (int k0 = 0; k0 < K; k0 += 16){
#pragma unroll
        for (int x = 0; x < 8; x++){
            int idx = tid + x*256;
            int m = idx >> 4, kk = idx & 15;
            sA[kk][m] = A[(size_t)(m0+m)*K + k0 + kk];
        }
#pragma unroll
        for (int x = 0; x < 4; x++){
            int idx = tid + x*256;
            int kk = idx >> 6, n = idx & 63;
            sB[kk][n] = Bm[(size_t)(k0+kk)*N + n0 + n];
        }
        __syncthreads();
#pragma unroll
        for (int kk = 0; kk < 16; kk++){
            float4 a0 = *(const float4*)&sA[kk][ty*8];
            float4 a1 = *(const float4*)&sA[kk][ty*8+4];
            float4 b0 = *(const float4*)&sB[kk][tx*4];
            float a[8] = {a0.x,a0.y,a0.z,a0.w,a1.x,a1.y,a1.z,a1.w};
            float bv[4] = {b0.x,b0.y,b0.z,b0.w};
#pragma unroll
            for (int i = 0; i < 8; i++)
#pragma unroll
                for (int j = 0; j < 4; j++) acc[i][j] += a[i]*bv[j];
        }
        __syncthreads();
    }
#pragma unroll
    for (int i = 0; i < 8; i++){
        int m = m0 + ty*8 + i;
#pragma unroll
        for (int j = 0; j < 4; j++){
            int n = n0 + tx*4 + j;
            float v = acc[i][j] + bias[n];
            if (EPI == 1) v = gelu_tanh(v);
            if (R) v += R[(size_t)m*N + n];
            C[(size_t)m*N + n] = v;
        }
    }
}

// ---------------- QKV GEMM with head-transposed scatter epilogue ----------------
// q_t/k_t/v_t layout: [(b*32+h)][n][24]. Q pre-scaled by SCALE_Q.
__global__ __launch_bounds__(256) void gemm_qkv(
    const float* __restrict__ A, const float* __restrict__ Bm,
    const float* __restrict__ bias,
    float* __restrict__ qt, float* __restrict__ kt, float* __restrict__ vt)
{
    const int M = 2048, N = 2304, K = 768;
    __shared__ float sA[16][132];
    __shared__ float sB[16][64];
    int m0 = blockIdx.y * 128;
    int n0 = blockIdx.x * 64;
    int tid = threadIdx.x;
    int ty = tid >> 4;
    int tx = tid & 15;
    float acc[8][4];
#pragma unroll
    for (int i = 0; i < 8; i++)
#pragma unroll
        for (int j = 0; j < 4; j++) acc[i][j] = 0.f;
    for (int k0 = 0; k0 < K; k0 += 16){
#pragma unroll
        for (int x = 0; x < 8; x++){
            int idx = tid + x*256;
            int m = idx >> 4, kk = idx & 15;
            sA[kk][m] = A[(size_t)(m0+m)*K + k0 + kk];
        }
#pragma unroll
        for (int x = 0; x < 4; x++){
            int idx = tid + x*256;
            int kk = idx >> 6, n = idx & 63;
            sB[kk][n] = Bm[(size_t)(k0+kk)*N + n0 + n];
        }
        __syncthreads();
#pragma unroll
        for (int kk = 0; kk < 16; kk++){
            float4 a0 = *(const float4*)&sA[kk][ty*8];
            float4 a1 = *(const float4*)&sA[kk][ty*8+4];
            float4 b0 = *(const float4*)&sB[kk][tx*4];
            float a[8] = {a0.x,a0.y,a0.z,a0.w,a1.x,a1.y,a1.z,a1.w};
            float bv[4] = {b0.x,b0.y,b0.z,b0.w};
#pragma unroll
            for (int i = 0; i < 8; i++)
#pragma unroll
                for (int j = 0; j < 4; j++) acc[i][j] += a[i]*bv[j];
        }
        __syncthreads();
    }
#pragma unroll
    for (int i = 0; i < 8; i++){
        int m = m0 + ty*8 + i;
        int b = m >> 8, l = m & 255;
#pragma unroll
        for (int j = 0; j < 4; j++){
            int n = n0 + tx*4 + j;
            float v = acc[i][j] + bias[n];
            int seg = n / 768;
            int nn = n - seg*768;
            int dd = nn >> 5, h = nn & 31;
            size_t idx = (((size_t)(b*32 + h))*256 + l)*24 + dd;
            if (seg == 0)      qt[idx] = v * SCALE_Q;
            else if (seg == 1) kt[idx] = v;
            else               vt[idx] = v;
        }
    }
}

// ---------------- QK kernel: per (b,h): QK[l][m] = q_t[l]·k_t[m] ----------------
// grid (4, 256): x -> (ltile, mtile) of 128x128; y -> bh
__global__ __launch_bounds__(256) void qk_kernel(
    const float* __restrict__ qt, const float* __restrict__ kt,
    float* __restrict__ qk)
{
    int bh = blockIdx.y;
    int l0 = (blockIdx.x >> 1) * 128;
    int m0 = (blockIdx.x & 1) * 128;
    __shared__ float sQ[24*132];
    __shared__ float sK[24*132];
    int tid = threadIdx.x;
    const float* qb = qt + (size_t)bh*6144 + (size_t)l0*24;
    const float* kb = kt + (size_t)bh*6144 + (size_t)m0*24;
    for (int i = tid; i < 3072; i += 256){
        int r = i / 24, d = i - r*24;
        sQ[d*132 + r] = qb[i];
        sK[d*132 + r] = kb[i];
    }
    __syncthreads();
    int tx = tid & 15, ty = tid >> 4;
    float acc[8][8];
#pragma unroll
    for (int i = 0; i < 8; i++)
#pragma unroll
        for (int j = 0; j < 8; j++) acc[i][j] = 0.f;
#pragma unroll 6
    for (int k = 0; k < 24; k++){
        float4 a0 = *(const float4*)&sQ[k*132 + ty*8];
        float4 a1 = *(const float4*)&sQ[k*132 + ty*8 + 4];
        float4 b0 = *(const float4*)&sK[k*132 + tx*8];
        float4 b1 = *(const float4*)&sK[k*132 + tx*8 + 4];
        float a[8] = {a0.x,a0.y,a0.z,a0.w,a1.x,a1.y,a1.z,a1.w};
        float b[8] = {b0.x,b0.y,b0.z,b0.w,b1.x,b1.y,b1.z,b1.w};
#pragma unroll
        for (int i = 0; i < 8; i++)
#pragma unroll
            for (int j = 0; j < 8; j++) acc[i][j] += a[i]*b[j];
    }
    float* out = qk + (size_t)bh*65536 + (size_t)l0*256 + m0;
#pragma unroll
    for (int i = 0; i < 8; i++){
        float* orow = out + (size_t)(ty*8 + i)*256 + tx*8;
        float4 o0 = make_float4(acc[i][0],acc[i][1],acc[i][2],acc[i][3]);
        float4 o1 = make_float4(acc[i][4],acc[i][5],acc[i][6],acc[i][7]);
        *(float4*)orow = o0;
        *(float4*)(orow+4) = o1;
    }
}

// ---------------- fused edge kernel: one CTA per (b,l) ----------------
// smem layout (floats)
#define OFF_WEG  0
#define OFF_WOE  4096
#define OFF_EW1  6144
#define OFF_EW2  10240
#define OFF_PAR  14336
#define OFF_HHAT 14848
#define OFF_GATE 23168
#define OFF_QKC  31488
#define OFF_X    33664
#define OFF_R    38016
#define OFF_MASK 42368
#define EK_FLOATS 42624
__global__ __launch_bounds__(256, 1) void edge_attn_kernel(
    const float* __restrict__ e_in, const float* __restrict__ mask,
    const float* __restrict__ qk,
    const float* __restrict__ W_eg, const float* __restrict__ b_eg,
    const float* __restrict__ W_oe, const float* __restrict__ b_oe,
    const float* __restrict__ eln_g, const float* __restrict__ eln_b,
    const float* __restrict__ ffn_g, const float* __restrict__ ffn_b,
    const float* __restrict__ eW1, const float* __restrict__ eb1,
    const float* __restrict__ eW2, const float* __restrict__ eb2,
    float* __restrict__ e_out, float* __restrict__ a_all)
{
    extern __shared__ float sm[];
    float* sWeg  = sm + OFF_WEG;
    float* sWoe  = sm + OFF_WOE;
    float* sEW1  = sm + OFF_EW1;
    float* sEW2  = sm + OFF_EW2;
    float* sPar  = sm + OFF_PAR;
    float* sHhat = sm + OFF_HHAT;   // [32][260]
    float* sGate = sm + OFF_GATE;   // [32][260]
    float* sQKc  = sm + OFF_QKC;    // [32][68]
    float* sX    = sm + OFF_X;      // [64][68] (k-major)
    float* sR    = sm + OFF_R;      // [64][68] (m-major)
    float* sMask = sm + OFF_MASK;   // [256]

    int tid  = threadIdx.x;
    int w    = tid >> 5;
    int lane = tid & 31;
    int row  = blockIdx.x;
    int b    = row >> 8;
    int l    = row & 255;
    size_t qkbase = ((size_t)b*32)*65536 + (size_t)l*256;

    for (int i = tid; i < 4096; i += 256){
        sWeg[i] = W_eg[i]; sEW1[i] = eW1[i]; sEW2[i] = eW2[i];
    }
    for (int i = tid; i < 2048; i += 256) sWoe[i] = W_oe[i];
    if (tid < 64){
        sPar[tid]     = b_eg[tid];
        sPar[64+tid]  = b_oe[tid];
        sPar[128+tid] = eb1[tid];
        sPar[192+tid] = eb2[tid];
        sPar[256+tid] = eln_g[tid];
        sPar[320+tid] = eln_b[tid];
        sPar[384+tid] = ffn_g[tid];
        sPar[448+tid] = ffn_b[tid];
    }
    const float* lg  = sPar+256; const float* lb  = sPar+320;
    const float* fg  = sPar+384; const float* fb  = sPar+448;
    int tn = tid & 15, tm = tid >> 4;

    for (int chunk = 0; chunk < 4; ++chunk){
        int m0 = chunk * 64;
        // ---- stage e chunk, mask, qk chunk ----
        for (int i = tid; i < 1024; i += 256){
            int mm = i >> 4, k4 = (i & 15) * 4;
            *(float4*)&sR[mm*68 + k4] =
                *(const float4*)&e_in[((size_t)row*256 + m0 + mm)*64 + k4];
        }
        if (tid < 64) sMask[m0+tid] = mask[(size_t)row*256 + m0 + tid];
        for (int i = tid; i < 512; i += 256){
            int h = i >> 4, mq = (i & 15) * 4;
            *(float4*)&sQKc[h*68 + mq] =
                *(const float4*)&qk[qkbase + (size_t)h*65536 + m0 + mq];
        }
        __syncthreads();

        // ---- LN1: warp per 8 edges ----
#pragma unroll
        for (int j = 0; j < 8; j++){
            int mm = w*8 + j;
            float e0 = sR[mm*68 + lane], e1 = sR[mm*68 + 32 + lane];
            float mean = warpSum(e0+e1) * (1.f/64.f);
            float d0 = e0-mean, d1 = e1-mean;
            float var = warpSum(d0*d0 + d1*d1) * (1.f/64.f);
            float rs = rsqrtf(var + 1e-5f);
            sX[lane*68 + mm]      = d0*rs*lg[lane]    + lb[lane];
            sX[(lane+32)*68 + mm] = d1*rs*lg[lane+32] + lb[lane+32];
        }
        __syncthreads();

        // ---- GEMM1: EG = X @ W_eg ----
        float acc[4][4];
#pragma unroll
        for (int i=0;i<4;i++)
#pragma unroll
            for (int j=0;j<4;j++) acc[i][j]=0.f;
#pragma unroll 8
        for (int k = 0; k < 64; k++){
            float4 a4 = *(const float4*)&sX[k*68 + tm*4];
            float4 b4 = *(const float4*)&sWeg[k*64 + tn*4];
            float a[4]={a4.x,a4.y,a4.z,a4.w}, bv[4]={b4.x,b4.y,b4.z,b4.w};
#pragma unroll
            for (int i=0;i<4;i++)
#pragma unroll
                for (int j=0;j<4;j++) acc[i][j] += a[i]*bv[j];
        }
        if (tn < 8){
#pragma unroll
            for (int j=0;j<4;j++){
                int h = tn*4 + j;
                float bb = sPar[h];
#pragma unroll
                for (int i=0;i<4;i++){
                    int mloc = tm*4 + i;
                    sHhat[h*260 + m0 + mloc] = acc[i][j] + bb + sQKc[h*68 + mloc];
                }
            }
        } else {
#pragma unroll
            for (int j=0;j<4;j++){
                int n = tn*4 + j;
                int h = n - 32;
                float bb = sPar[n];
#pragma unroll
                for (int i=0;i<4;i++){
                    int mloc = tm*4 + i;
                    float g = acc[i][j] + bb + sMask[m0 + mloc];
                    sGate[h*260 + m0 + mloc] = sigmoidf_(g);
                }
            }
        }
        __syncthreads();

        // ---- GEMM2: e_att = H_hat @ W_oe ; r = e + e_att + b_oe ----
#pragma unroll
        for (int i=0;i<4;i++)
#pragma unroll
            for (int j=0;j<4;j++) acc[i][j]=0.f;
#pragma unroll 8
        for (int k = 0; k < 32; k++){
            float4 a4 = *(const float4*)&sHhat[k*260 + m0 + tm*4];
            float4 b4 = *(const float4*)&sWoe[k*64 + tn*4];
            float a[4]={a4.x,a4.y,a4.z,a4.w}, bv[4]={b4.x,b4.y,b4.z,b4.w};
#pragma unroll
            for (int i=0;i<4;i++)
#pragma unroll
                for (int j=0;j<4;j++) acc[i][j] += a[i]*bv[j];
        }
#pragma unroll
        for (int i=0;i<4;i++){
            float4 r = *(float4*)&sR[(tm*4+i)*68 + tn*4];
            r.x += acc[i][0] + sPar[64 + tn*4 + 0];
            r.y += acc[i][1] + sPar[64 + tn*4 + 1];
            r.z += acc[i][2] + sPar[64 + tn*4 + 2];
            r.w += acc[i][3] + sPar[64 + tn*4 + 3];
            *(float4*)&sR[(tm*4+i)*68 + tn*4] = r;
        }
        __syncthreads();

        // ---- LN2 on r -> sX ----
#pragma unroll
        for (int j = 0; j < 8; j++){
            int mm = w*8 + j;
            float e0 = sR[mm*68 + lane], e1 = sR[mm*68 + 32 + lane];
            float mean = warpSum(e0+e1) * (1.f/64.f);
            float d0 = e0-mean, d1 = e1-mean;
            float var = warpSum(d0*d0 + d1*d1) * (1.f/64.f);
            float rs = rsqrtf(var + 1e-5f);
            sX[lane*68 + mm]      = d0*rs*fg[lane]    + fb[lane];
            sX[(lane+32)*68 + mm] = d1*rs*fg[lane+32] + fb[lane+32];
        }
        __syncthreads();

        // ---- GEMM3: T = gelu(X2 @ eW1 + b1) -> sX (transposed) ----
#pragma unroll
        for (int i=0;i<4;i++)
#pragma unroll
            for (int j=0;j<4;j++) acc[i][j]=0.f;
#pragma unroll 8
        for (int k = 0; k < 64; k++){
            float4 a4 = *(const float4*)&sX[k*68 + tm*4];
            float4 b4 = *(const float4*)&sEW1[k*64 + tn*4];
            float a[4]={a4.x,a4.y,a4.z,a4.w}, bv[4]={b4.x,b4.y,b4.z,b4.w};
#pragma unroll
            for (int i=0;i<4;i++)
#pragma unroll
                for (int j=0;j<4;j++) acc[i][j] += a[i]*bv[j];
        }
        __syncthreads();  // all reads of sX done before overwrite
#pragma unroll
        for (int j=0;j<4;j++){
            int n = tn*4 + j;
            float bb = sPar[128 + n];
#pragma unroll
            for (int i=0;i<4;i++)
                sX[n*68 + tm*4 + i] = gelu_tanh(acc[i][j] + bb);
        }
        __syncthreads();

        // ---- GEMM4: O = T @ eW2 + b2 ; e_out = r + O ----
#pragma unroll
        for (int i=0;i<4;i++)
#pragma unroll
            for (int j=0;j<4;j++) acc[i][j]=0.f;
#pragma unroll 8
        for (int k = 0; k < 64; k++){
            float4 a4 = *(const float4*)&sX[k*68 + tm*4];
            float4 b4 = *(const float4*)&sEW2[k*64 + tn*4];
            float a[4]={a4.x,a4.y,a4.z,a4.w}, bv[4]={b4.x,b4.y,b4.z,b4.w};
#pragma unroll
            for (int i=0;i<4;i++)
#pragma unroll
                for (int j=0;j<4;j++) acc[i][j] += a[i]*bv[j];
        }
#pragma unroll
        for (int i=0;i<4;i++){
            int mg = m0 + tm*4 + i;
            float4 rr = *(const float4*)&sR[(tm*4+i)*68 + tn*4];
            float4 o;
            o.x = acc[i][0] + sPar[192 + tn*4 + 0] + rr.x;
            o.y = acc[i][1] + sPar[192 + tn*4 + 1] + rr.y;
            o.z = acc[i][2] + sPar[192 + tn*4 + 2] + rr.z;
            o.w = acc[i][3] + sPar[192 + tn*4 + 3] + rr.w;
            *(float4*)&e_out[((size_t)row*256 + mg)*64 + tn*4] = o;
        }
        __syncthreads();
    }

    // ---- softmax over m per head + fold gates & degree scaler ----
#pragma unroll
    for (int hi = 0; hi < 4; hi++){
        int h = w + hi*8;
        float p[8], g[8];
        float mx = -3.4e38f;
#pragma unroll
        for (int j = 0; j < 8; j++){
            int m = j*32 + lane;
            p[j] = sHhat[h*260 + m] + sMask[m];
            mx = fmaxf(mx, p[j]);
        }
        mx = warpMax(mx);
        float s = 0.f, gs = 0.f;
#pragma unroll
        for (int j = 0; j < 8; j++){
            p[j] = __expf(p[j] - mx);
            s += p[j];
            g[j] = sGate[h*260 + j*32 + lane];
            gs += g[j];
        }
        s = warpSum(s); gs = warpSum(gs);
        float c = (1.f / s) * log1pf(gs);
        float* ao = a_all + (((size_t)(b*32 + h))*256 + l)*256;
#pragma unroll
        for (int j = 0; j < 8; j++)
            ao[j*32 + lane] = p[j] * g[j] * c;
    }
}

// ---------------- AV kernel: per (b,h), V_att = A' @ V ----------------
// grid (4, 256): x -> l-tile of 64; y -> bh. dynamic smem.
#define AV_FLOATS (64*260 + 24*260)
__global__ __launch_bounds__(256) void av_kernel(
    const float* __restrict__ a_all, const float* __restrict__ vt,
    float* __restrict__ vatt)
{
    extern __shared__ float sm[];
    float* sA = sm;            // [64][260]
    float* sV = sm + 64*260;   // [24][260]
    int bh = blockIdx.y;
    int l0 = blockIdx.x * 64;
    int b = bh >> 5, h = bh & 31;
    int tid = threadIdx.x;
    const float* ab = a_all + (size_t)bh*65536 + (size_t)l0*256;
    for (int i = tid; i < 4096; i += 256){
        int ll = i >> 6, m = (i & 63) * 4;
        *(float4*)&sA[ll*260 + m] = *(const float4*)&ab[(size_t)ll*256 + m];
    }
    const float* vb = vt + (size_t)bh*6144;
    for (int i = tid; i < 6144; i += 256){
        int m = i / 24, dd = i - m*24;
        sV[dd*260 + m] = vb[i];
    }
    __syncthreads();
    int w = tid >> 5, lane = tid & 31;
    if (lane < 24){
        const float* vr = &sV[lane*260];
#pragma unroll
        for (int j = 0; j < 8; j++){
            int ll = w*8 + j;
            const float* ar = &sA[ll*260];
            float acc = 0.f;
#pragma unroll 8
            for (int m = 0; m < 256; m += 4){
                float4 a = *(const float4*)&ar[m];
                float4 v = *(const float4*)&vr[m];
                acc += a.x*v.x + a.y*v.y + a.z*v.z + a.w*v.w;
            }
            vatt[(size_t)(b*256 + l0 + ll)*768 + lane*32 + h] = acc;
        }
    }
}

// ---------------- host ----------------
extern "C" void kernel_launch(void* const* d_in, const int* in_sizes, int n_in,
                              void* d_out, int out_size)
{
    const float* h_in   = (const float*)d_in[0];
    const float* e_in   = (const float*)d_in[1];
    const float* mask   = (const float*)d_in[2];
    const float* ln_h_g = (const float*)d_in[3];
    const float* ln_h_b = (const float*)d_in[4];
    const float* ln_e_g = (const float*)d_in[5];
    const float* ln_e_b = (const float*)d_in[6];
    const float* W_qkv  = (const float*)d_in[7];
    const float* b_qkv  = (const float*)d_in[8];
    const float* W_eg   = (const float*)d_in[9];
    const float* b_eg   = (const float*)d_in[10];
    const float* W_oh   = (const float*)d_in[11];
    const float* b_oh   = (const float*)d_in[12];
    const float* W_oe   = (const float*)d_in[13];
    const float* b_oe   = (const float*)d_in[14];
    const float* nffn_g = (const float*)d_in[15];
    const float* nffn_b = (const float*)d_in[16];
    const float* nW1    = (const float*)d_in[17];
    const float* nb1    = (const float*)d_in[18];
    const float* nW2    = (const float*)d_in[19];
    const float* nb2    = (const float*)d_in[20];
    const float* effn_g = (const float*)d_in[21];
    const float* effn_b = (const float*)d_in[22];
    const float* eW1    = (const float*)d_in[23];
    const float* eb1    = (const float*)d_in[24];
    const float* eW2    = (const float*)d_in[25];
    const float* eb2    = (const float*)d_in[26];

    float* out_h = (float*)d_out;
    float* out_e = out_h + (size_t)ROWS * DD_;

    float *hln, *qt, *kt, *vt, *qk, *aa, *vatt, *hmid, *hln2, *tbuf;
    cudaGetSymbolAddress((void**)&hln,  g_hln);
    cudaGetSymbolAddress((void**)&qt,   g_qt);
    cudaGetSymbolAddress((void**)&kt,   g_kt);
    cudaGetSymbolAddress((void**)&vt,   g_vt);
    cudaGetSymbolAddress((void**)&qk,   g_qk);
    cudaGetSymbolAddress((void**)&aa,   g_a);
    cudaGetSymbolAddress((void**)&vatt, g_vatt);
    cudaGetSymbolAddress((void**)&hmid, g_hmid);
    cudaGetSymbolAddress((void**)&hln2, g_hln2);
    cudaGetSymbolAddress((void**)&tbuf, g_t);

    cudaFuncSetAttribute(edge_attn_kernel,
                         cudaFuncAttributeMaxDynamicSharedMemorySize,
                         EK_FLOATS * 4);
    cudaFuncSetAttribute(av_kernel,
                         cudaFuncAttributeMaxDynamicSharedMemorySize,
                         AV_FLOATS * 4);

    // 1) h layernorm
    ln768_kernel<<<ROWS, 256>>>(h_in, ln_h_g, ln_h_b, hln);

    // 2) QKV GEMM with transposed scatter
    gemm_qkv<<<dim3(36, 16), 256>>>(hln, W_qkv, b_qkv, qt, kt, vt);

    // 3) QK = Q K^T per head
    qk_kernel<<<dim3(4, 256), 256>>>(qt, kt, qk);

    // 4) fused edge attention + edge FFN -> e_out, A'
    edge_attn_kernel<<<ROWS, 256, EK_FLOATS * 4>>>(
        e_in, mask, qk,
        W_eg, b_eg, W_oe, b_oe,
        ln_e_g, ln_e_b, effn_g, effn_b,
        eW1, eb1, eW2, eb2,
        out_e, aa);

    // 5) V_att = A' @ V (degree scaler folded into A')
    av_kernel<<<dim3(4, 256), 256, AV_FLOATS * 4>>>(aa, vt, vatt);

    // 6) h_mid = h + V_att @ W_oh + b_oh
    gemm_epi<0><<<dim3(12, 16), 256>>>(vatt, W_oh, b_oh, h_in, hmid,
                                       ROWS, DD_, DD_);

    // 7) node FFN
    ln768_kernel<<<ROWS, 256>>>(hmid, nffn_g, nffn_b, hln2);
    gemm_epi<1><<<dim3(12, 16), 256>>>(hln2, nW1, nb1, nullptr, tbuf,
                                       ROWS, DD_, DD_);
    gemm_epi<0><<<dim3(12, 16), 256>>>(tbuf, nW2, nb2, hmid, out_h,
                                       ROWS, DD_, DD_);
}

// round 4
// speedup vs baseline: 1.3630x; 1.1825x over previous
#include <cuda_runtime.h>
#include <cstddef>

// ---------------- problem constants ----------------
#define BB 8
#define NN 256
#define DD_ 768
#define ROWS (BB*NN)     // 2048
#define SCALE_Q 0.20412414523193154f   // 24^-0.5
#define FULLMASK 0xffffffffu

// ---------------- scratch (device globals; no allocation) ----------------
__device__ float g_hln [ROWS*DD_];
__device__ float g_qt  [8*32*256*24];
__device__ float g_kt  [8*32*256*24];
__device__ float g_vt  [8*32*256*24];
__device__ float g_qk  [8*32*256*256];
__device__ float g_a   [8*32*256*256];
__device__ float g_vatt[ROWS*DD_];
__device__ float g_hmid[ROWS*DD_];
__device__ float g_hln2[ROWS*DD_];
__device__ float g_t   [ROWS*DD_];

// ---------------- helpers ----------------
__device__ __forceinline__ float warpSum(float v){
#pragma unroll
    for (int o = 16; o; o >>= 1) v += __shfl_xor_sync(FULLMASK, v, o);
    return v;
}
__device__ __forceinline__ float warpMax(float v){
#pragma unroll
    for (int o = 16; o; o >>= 1) v = fmaxf(v, __shfl_xor_sync(FULLMASK, v, o));
    return v;
}
__device__ __forceinline__ float gelu_tanh(float x){
    float y = 0.7978845608028654f * (x + 0.044715f * x * x * x);
    y = fminf(fmaxf(y, -30.f), 30.f);
    float t = __expf(2.f * y);
    float th = (t - 1.f) / (t + 1.f);
    return 0.5f * x * (1.f + th);
}
__device__ __forceinline__ float sigmoidf_(float x){
    return 1.f / (1.f + __expf(-x));
}

// ---------------- LayerNorm over 768 ----------------
__global__ __launch_bounds__(256) void ln768_kernel(
    const float* __restrict__ x, const float* __restrict__ g,
    const float* __restrict__ b, float* __restrict__ y)
{
    int row = blockIdx.x;
    int tid = threadIdx.x;
    const float* xr = x + (size_t)row * DD_;
    float*       yr = y + (size_t)row * DD_;
    float v0 = xr[tid], v1 = xr[tid+256], v2 = xr[tid+512];
    __shared__ float red[8];
    float s = warpSum(v0 + v1 + v2);
    if ((tid & 31) == 0) red[tid >> 5] = s;
    __syncthreads();
    float tot = 0.f;
#pragma unroll
    for (int i = 0; i < 8; i++) tot += red[i];
    __syncthreads();
    float mean = tot * (1.f/768.f);
    float d0 = v0-mean, d1 = v1-mean, d2 = v2-mean;
    float q = warpSum(d0*d0 + d1*d1 + d2*d2);
    if ((tid & 31) == 0) red[tid >> 5] = q;
    __syncthreads();
    float vt = 0.f;
#pragma unroll
    for (int i = 0; i < 8; i++) vt += red[i];
    float rstd = rsqrtf(vt * (1.f/768.f) + 1e-5f);
    yr[tid]     = d0*rstd*g[tid]     + b[tid];
    yr[tid+256] = d1*rstd*g[tid+256] + b[tid+256];
    yr[tid+512] = d2*rstd*g[tid+512] + b[tid+512];
}

// ---------------- fp32 GEMM 128x128 tile, 8x8/thread ----------------
template<int EPI>  // 0 none, 1 gelu
__global__ __launch_bounds__(256) void gemm128(
    const float* __restrict__ A, const float* __restrict__ Bm,
    const float* __restrict__ bias, const float* __restrict__ R,
    float* __restrict__ C, int M, int N, int K)
{
    __shared__ float sA[16][136];
    __shared__ float sB[16][136];
    int m0 = blockIdx.y * 128;
    int n0 = blockIdx.x * 128;
    int tid = threadIdx.x;
    int ar = tid >> 1, ak = (tid & 1) * 8;
    int bk = tid >> 4, bn = (tid & 15) * 8;
    int ty = tid >> 4, tx = tid & 15;
    float acc[8][8];
#pragma unroll
    for (int i = 0; i < 8; i++)
#pragma unroll
        for (int j = 0; j < 8; j++) acc[i][j] = 0.f;

    for (int k0 = 0; k0 < K; k0 += 16){
        const float* ap = &A[(size_t)(m0+ar)*K + k0 + ak];
        float4 a0 = *(const float4*)ap;
        float4 a1 = *(const float4*)(ap+4);
        sA[ak+0][ar]=a0.x; sA[ak+1][ar]=a0.y; sA[ak+2][ar]=a0.z; sA[ak+3][ar]=a0.w;
        sA[ak+4][ar]=a1.x; sA[ak+5][ar]=a1.y; sA[ak+6][ar]=a1.z; sA[ak+7][ar]=a1.w;
        const float* bp = &Bm[(size_t)(k0+bk)*N + n0 + bn];
        *(float4*)&sB[bk][bn]   = *(const float4*)bp;
        *(float4*)&sB[bk][bn+4] = *(const float4*)(bp+4);
        __syncthreads();
#pragma unroll
        for (int kk = 0; kk < 16; kk++){
            float4 x0 = *(const float4*)&sA[kk][ty*8];
            float4 x1 = *(const float4*)&sA[kk][ty*8+4];
            float4 y0 = *(const float4*)&sB[kk][tx*8];
            float4 y1 = *(const float4*)&sB[kk][tx*8+4];
            float a[8] = {x0.x,x0.y,x0.z,x0.w,x1.x,x1.y,x1.z,x1.w};
            float b[8] = {y0.x,y0.y,y0.z,y0.w,y1.x,y1.y,y1.z,y1.w};
#pragma unroll
            for (int i = 0; i < 8; i++)
#pragma unroll
                for (int j = 0; j < 8; j++) acc[i][j] += a[i]*b[j];
        }
        __syncthreads();
    }
#pragma unroll
    for (int i = 0; i < 8; i++){
        int m = m0 + ty*8 + i;
#pragma unroll
        for (int j = 0; j < 8; j++){
            int n = n0 + tx*8 + j;
            float v = acc[i][j] + bias[n];
            if (EPI == 1) v = gelu_tanh(v);
            if (R) v += R[(size_t)m*N + n];
            C[(size_t)m*N + n] = v;
        }
    }
}

// ---------------- QKV GEMM (128x128) with head-transposed scatter ----------------
__global__ __launch_bounds__(256) void gemm_qkv(
    const float* __restrict__ A, const float* __restrict__ Bm,
    const float* __restrict__ bias,
    float* __restrict__ qt, float* __restrict__ kt, float* __restrict__ vt)
{
    const int N = 2304, K = 768;
    __shared__ float sA[16][136];
    __shared__ float sB[16][136];
    int m0 = blockIdx.y * 128;
    int n0 = blockIdx.x * 128;
    int tid = threadIdx.x;
    int ar = tid >> 1, ak = (tid & 1) * 8;
    int bk = tid >> 4, bn = (tid & 15) * 8;
    int ty = tid >> 4, tx = tid & 15;
    float acc[8][8];
#pragma unroll
    for (int i = 0; i < 8; i++)
#pragma unroll
        for (int j = 0; j < 8; j++) acc[i][j] = 0.f;

    for (int k0 = 0; k0 < K; k0 += 16){
        const float* ap = &A[(size_t)(m0+ar)*K + k0 + ak];
        float4 a0 = *(const float4*)ap;
        float4 a1 = *(const float4*)(ap+4);
        sA[ak+0][ar]=a0.x; sA[ak+1][ar]=a0.y; sA[ak+2][ar]=a0.z; sA[ak+3][ar]=a0.w;
        sA[ak+4][ar]=a1.x; sA[ak+5][ar]=a1.y; sA[ak+6][ar]=a1.z; sA[ak+7][ar]=a1.w;
        const float* bp = &Bm[(size_t)(k0+bk)*N + n0 + bn];
        *(float4*)&sB[bk][bn]   = *(const float4*)bp;
        *(float4*)&sB[bk][bn+4] = *(const float4*)(bp+4);
        __syncthreads();
#pragma unroll
        for (int kk = 0; kk < 16; kk++){
            float4 x0 = *(const float4*)&sA[kk][ty*8];
            float4 x1 = *(const float4*)&sA[kk][ty*8+4];
            float4 y0 = *(const float4*)&sB[kk][tx*8];
            float4 y1 = *(const float4*)&sB[kk][tx*8+4];
            float a[8] = {x0.x,x0.y,x0.z,x0.w,x1.x,x1.y,x1.z,x1.w};
            float b[8] = {y0.x,y0.y,y0.z,y0.w,y1.x,y1.y,y1.z,y1.w};
#pragma unroll
            for (int i = 0; i < 8; i++)
#pragma unroll
                for (int j = 0; j < 8; j++) acc[i][j] += a[i]*b[j];
        }
        __syncthreads();
    }
#pragma unroll
    for (int i = 0; i < 8; i++){
        int m = m0 + ty*8 + i;
        int b = m >> 8, l = m & 255;
#pragma unroll
        for (int j = 0; j < 8; j++){
            int n = n0 + tx*8 + j;
            float v = acc[i][j] + bias[n];
            int seg = n / 768;
            int nn = n - seg*768;
            int dd = nn >> 5, h = nn & 31;
            size_t idx = (((size_t)(b*32 + h))*256 + l)*24 + dd;
            if (seg == 0)      qt[idx] = v * SCALE_Q;
            else if (seg == 1) kt[idx] = v;
            else               vt[idx] = v;
        }
    }
}

// ---------------- QK kernel ----------------
__global__ __launch_bounds__(256) void qk_kernel(
    const float* __restrict__ qt, const float* __restrict__ kt,
    float* __restrict__ qk)
{
    int bh = blockIdx.y;
    int l0 = (blockIdx.x >> 1) * 128;
    int m0 = (blockIdx.x & 1) * 128;
    __shared__ float sQ[24*132];
    __shared__ float sK[24*132];
    int tid = threadIdx.x;
    const float* qb = qt + (size_t)bh*6144 + (size_t)l0*24;
    const float* kb = kt + (size_t)bh*6144 + (size_t)m0*24;
    for (int i = tid; i < 3072; i += 256){
        int r = i / 24, d = i - r*24;
        sQ[d*132 + r] = qb[i];
        sK[d*132 + r] = kb[i];
    }
    __syncthreads();
    int tx = tid & 15, ty = tid >> 4;
    float acc[8][8];
#pragma unroll
    for (int i = 0; i < 8; i++)
#pragma unroll
        for (int j = 0; j < 8; j++) acc[i][j] = 0.f;
#pragma unroll 6
    for (int k = 0; k < 24; k++){
        float4 a0 = *(const float4*)&sQ[k*132 + ty*8];
        float4 a1 = *(const float4*)&sQ[k*132 + ty*8 + 4];
        float4 b0 = *(const float4*)&sK[k*132 + tx*8];
        float4 b1 = *(const float4*)&sK[k*132 + tx*8 + 4];
        float a[8] = {a0.x,a0.y,a0.z,a0.w,a1.x,a1.y,a1.z,a1.w};
        float b[8] = {b0.x,b0.y,b0.z,b0.w,b1.x,b1.y,b1.z,b1.w};
#pragma unroll
        for (int i = 0; i < 8; i++)
#pragma unroll
            for (int j = 0; j < 8; j++) acc[i][j] += a[i]*b[j];
    }
    float* out = qk + (size_t)bh*65536 + (size_t)l0*256 + m0;
#pragma unroll
    for (int i = 0; i < 8; i++){
        float* orow = out + (size_t)(ty*8 + i)*256 + tx*8;
        *(float4*)orow     = make_float4(acc[i][0],acc[i][1],acc[i][2],acc[i][3]);
        *(float4*)(orow+4) = make_float4(acc[i][4],acc[i][5],acc[i][6],acc[i][7]);
    }
}

// ---------------- fused edge kernel: one CTA per (b,l), 512 threads ----------------
// Two groups of 256 threads process 2 chunks each concurrently.
#define OFF_WEG  0
#define OFF_WOE  4096
#define OFF_EW1  6144
#define OFF_EW2  10240
#define OFF_PAR  14336
#define OFF_HHAT 14848          // [32][260]
#define OFF_GATE 23168          // [32][260]
#define OFF_MASK 31488          // [256]
#define OFF_GRP  31744
#define GRP_SZ   10880          // per group: QKc 2176 + X 4352 + R 4352
#define EK_FLOATS (OFF_GRP + 2*GRP_SZ)   // 53504 floats = 214016 B
__global__ __launch_bounds__(512, 1) void edge_attn_kernel(
    const float* __restrict__ e_in, const float* __restrict__ mask,
    const float* __restrict__ qk,
    const float* __restrict__ W_eg, const float* __restrict__ b_eg,
    const float* __restrict__ W_oe, const float* __restrict__ b_oe,
    const float* __restrict__ eln_g, const float* __restrict__ eln_b,
    const float* __restrict__ ffn_g, const float* __restrict__ ffn_b,
    const float* __restrict__ eW1, const float* __restrict__ eb1,
    const float* __restrict__ eW2, const float* __restrict__ eb2,
    float* __restrict__ e_out, float* __restrict__ a_all)
{
    extern __shared__ float sm[];
    float* sWeg  = sm + OFF_WEG;
    float* sWoe  = sm + OFF_WOE;
    float* sEW1  = sm + OFF_EW1;
    float* sEW2  = sm + OFF_EW2;
    float* sPar  = sm + OFF_PAR;
    float* sHhat = sm + OFF_HHAT;
    float* sGate = sm + OFF_GATE;
    float* sMask = sm + OFF_MASK;

    int tid  = threadIdx.x;
    int grp  = tid >> 8;
    int t    = tid & 255;
    int w    = tid >> 5;       // 0..15
    int lane = tid & 31;
    int wg   = t >> 5;         // warp within group 0..7
    int row  = blockIdx.x;
    int b    = row >> 8;
    int l    = row & 255;
    size_t qkbase = ((size_t)b*32)*65536 + (size_t)l*256;

    float* sQKc = sm + OFF_GRP + grp*GRP_SZ;        // [32][68]
    float* sX   = sQKc + 2176;                      // [64][68]
    float* sR   = sX + 4352;                        // [64][68]

    for (int i = tid; i < 4096; i += 512){
        sWeg[i] = W_eg[i]; sEW1[i] = eW1[i]; sEW2[i] = eW2[i];
    }
    for (int i = tid; i < 2048; i += 512) sWoe[i] = W_oe[i];
    if (tid < 64){
        sPar[tid]     = b_eg[tid];
        sPar[64+tid]  = b_oe[tid];
        sPar[128+tid] = eb1[tid];
        sPar[192+tid] = eb2[tid];
        sPar[256+tid] = eln_g[tid];
        sPar[320+tid] = eln_b[tid];
        sPar[384+tid] = ffn_g[tid];
        sPar[448+tid] = ffn_b[tid];
    }
    const float* lg  = sPar+256; const float* lb  = sPar+320;
    const float* fg  = sPar+384; const float* fb  = sPar+448;
    int tn = t & 15, tm = t >> 4;

    for (int c = 0; c < 2; ++c){
        int m0 = (grp*2 + c) * 64;
        // ---- stage e chunk, mask, qk chunk ----
        for (int i = t; i < 1024; i += 256){
            int mm = i >> 4, k4 = (i & 15) * 4;
            *(float4*)&sR[mm*68 + k4] =
                *(const float4*)&e_in[((size_t)row*256 + m0 + mm)*64 + k4];
        }
        if (t < 64) sMask[m0+t] = mask[(size_t)row*256 + m0 + t];
        for (int i = t; i < 512; i += 256){
            int h = i >> 4, mq = (i & 15) * 4;
            *(float4*)&sQKc[h*68 + mq] =
                *(const float4*)&qk[qkbase + (size_t)h*65536 + m0 + mq];
        }
        __syncthreads();

        // ---- LN1 ----
#pragma unroll
        for (int j = 0; j < 8; j++){
            int mm = wg*8 + j;
            float e0 = sR[mm*68 + lane], e1 = sR[mm*68 + 32 + lane];
            float mean = warpSum(e0+e1) * (1.f/64.f);
            float d0 = e0-mean, d1 = e1-mean;
            float var = warpSum(d0*d0 + d1*d1) * (1.f/64.f);
            float rs = rsqrtf(var + 1e-5f);
            sX[lane*68 + mm]      = d0*rs*lg[lane]    + lb[lane];
            sX[(lane+32)*68 + mm] = d1*rs*lg[lane+32] + lb[lane+32];
        }
        __syncthreads();

        // ---- GEMM1: EG = X @ W_eg ----
        float acc[4][4];
#pragma unroll
        for (int i=0;i<4;i++)
#pragma unroll
            for (int j=0;j<4;j++) acc[i][j]=0.f;
#pragma unroll 8
        for (int k = 0; k < 64; k++){
            float4 a4 = *(const float4*)&sX[k*68 + tm*4];
            float4 b4 = *(const float4*)&sWeg[k*64 + tn*4];
            float a[4]={a4.x,a4.y,a4.z,a4.w}, bv[4]={b4.x,b4.y,b4.z,b4.w};
#pragma unroll
            for (int i=0;i<4;i++)
#pragma unroll
                for (int j=0;j<4;j++) acc[i][j] += a[i]*bv[j];
        }
        if (tn < 8){
#pragma unroll
            for (int j=0;j<4;j++){
                int h = tn*4 + j;
                float bb = sPar[h];
#pragma unroll
                for (int i=0;i<4;i++){
                    int mloc = tm*4 + i;
                    sHhat[h*260 + m0 + mloc] = acc[i][j] + bb + sQKc[h*68 + mloc];
                }
            }
        } else {
#pragma unroll
            for (int j=0;j<4;j++){
                int n = tn*4 + j;
                int h = n - 32;
                float bb = sPar[n];
#pragma unroll
                for (int i=0;i<4;i++){
                    int mloc = tm*4 + i;
                    float g = acc[i][j] + bb + sMask[m0 + mloc];
                    sGate[h*260 + m0 + mloc] = sigmoidf_(g);
                }
            }
        }
        __syncthreads();

        // ---- GEMM2: e_att = H_hat @ W_oe ; r += ----
#pragma unroll
        for (int i=0;i<4;i++)
#pragma unroll
            for (int j=0;j<4;j++) acc[i][j]=0.f;
#pragma unroll 8
        for (int k = 0; k < 32; k++){
            float4 a4 = *(const float4*)&sHhat[k*260 + m0 + tm*4];
            float4 b4 = *(const float4*)&sWoe[k*64 + tn*4];
            float a[4]={a4.x,a4.y,a4.z,a4.w}, bv[4]={b4.x,b4.y,b4.z,b4.w};
#pragma unroll
            for (int i=0;i<4;i++)
#pragma unroll
                for (int j=0;j<4;j++) acc[i][j] += a[i]*bv[j];
        }
#pragma unroll
        for (int i=0;i<4;i++){
            float4 r = *(float4*)&sR[(tm*4+i)*68 + tn*4];
            r.x += acc[i][0] + sPar[64 + tn*4 + 0];
            r.y += acc[i][1] + sPar[64 + tn*4 + 1];
            r.z += acc[i][2] + sPar[64 + tn*4 + 2];
            r.w += acc[i][3] + sPar[64 + tn*4 + 3];
            *(float4*)&sR[(tm*4+i)*68 + tn*4] = r;
        }
        __syncthreads();

        // ---- LN2 ----
#pragma unroll
        for (int j = 0; j < 8; j++){
            int mm = wg*8 + j;
            float e0 = sR[mm*68 + lane], e1 = sR[mm*68 + 32 + lane];
            float mean = warpSum(e0+e1) * (1.f/64.f);
            float d0 = e0-mean, d1 = e1-mean;
            float var = warpSum(d0*d0 + d1*d1) * (1.f/64.f);
            float rs = rsqrtf(var + 1e-5f);
            sX[lane*68 + mm]      = d0*rs*fg[lane]    + fb[lane];
            sX[(lane+32)*68 + mm] = d1*rs*fg[lane+32] + fb[lane+32];
        }
        __syncthreads();

        // ---- GEMM3: T = gelu(X2 @ eW1 + b1) ----
#pragma unroll
        for (int i=0;i<4;i++)
#pragma unroll
            for (int j=0;j<4;j++) acc[i][j]=0.f;
#pragma unroll 8
        for (int k = 0; k < 64; k++){
            float4 a4 = *(const float4*)&sX[k*68 + tm*4];
            float4 b4 = *(const float4*)&sEW1[k*64 + tn*4];
            float a[4]={a4.x,a4.y,a4.z,a4.w}, bv[4]={b4.x,b4.y,b4.z,b4.w};
#pragma unroll
            for (int i=0;i<4;i++)
#pragma unroll
                for (int j=0;j<4;j++) acc[i][j] += a[i]*bv[j];
        }
        __syncthreads();
#pragma unroll
        for (int j=0;j<4;j++){
            int n = tn*4 + j;
            float bb = sPar[128 + n];
#pragma unroll
            for (int i=0;i<4;i++)
                sX[n*68 + tm*4 + i] = gelu_tanh(acc[i][j] + bb);
        }
        __syncthreads();

        // ---- GEMM4: O = T @ eW2 + b2 ; e_out = r + O ----
#pragma unroll
        for (int i=0;i<4;i++)
#pragma unroll
            for (int j=0;j<4;j++) acc[i][j]=0.f;
#pragma unroll 8
        for (int k = 0; k < 64; k++){
            float4 a4 = *(const float4*)&sX[k*68 + tm*4];
            float4 b4 = *(const float4*)&sEW2[k*64 + tn*4];
            float a[4]={a4.x,a4.y,a4.z,a4.w}, bv[4]={b4.x,b4.y,b4.z,b4.w};
#pragma unroll
            for (int i=0;i<4;i++)
#pragma unroll
                for (int j=0;j<4;j++) acc[i][j] += a[i]*bv[j];
        }
#pragma unroll
        for (int i=0;i<4;i++){
            int mg = m0 + tm*4 + i;
            float4 rr = *(const float4*)&sR[(tm*4+i)*68 + tn*4];
            float4 o;
            o.x = acc[i][0] + sPar[192 + tn*4 + 0] + rr.x;
            o.y = acc[i][1] + sPar[192 + tn*4 + 1] + rr.y;
            o.z = acc[i][2] + sPar[192 + tn*4 + 2] + rr.z;
            o.w = acc[i][3] + sPar[192 + tn*4 + 3] + rr.w;
            *(float4*)&e_out[((size_t)row*256 + mg)*64 + tn*4] = o;
        }
        __syncthreads();
    }

    // ---- softmax over m per head, fold gates & degree ----
#pragma unroll
    for (int hi = 0; hi < 2; hi++){
        int h = w + hi*16;
        float p[8], g[8];
        float mx = -3.4e38f;
#pragma unroll
        for (int j = 0; j < 8; j++){
            int m = j*32 + lane;
            p[j] = sHhat[h*260 + m] + sMask[m];
            mx = fmaxf(mx, p[j]);
        }
        mx = warpMax(mx);
        float s = 0.f, gs = 0.f;
#pragma unroll
        for (int j = 0; j < 8; j++){
            p[j] = __expf(p[j] - mx);
            s += p[j];
            g[j] = sGate[h*260 + j*32 + lane];
            gs += g[j];
        }
        s = warpSum(s); gs = warpSum(gs);
        float c = (1.f / s) * log1pf(gs);
        float* ao = a_all + (((size_t)(b*32 + h))*256 + l)*256;
#pragma unroll
        for (int j = 0; j < 8; j++)
            ao[j*32 + lane] = p[j] * g[j] * c;
    }
}

// ---------------- AV kernel ----------------
#define AV_FLOATS (64*260 + 24*260)
__global__ __launch_bounds__(256) void av_kernel(
    const float* __restrict__ a_all, const float* __restrict__ vt,
    float* __restrict__ vatt)
{
    extern __shared__ float sm[];
    float* sA = sm;
    float* sV = sm + 64*260;
    int bh = blockIdx.y;
    int l0 = blockIdx.x * 64;
    int b = bh >> 5, h = bh & 31;
    int tid = threadIdx.x;
    const float* ab = a_all + (size_t)bh*65536 + (size_t)l0*256;
    for (int i = tid; i < 4096; i += 256){
        int ll = i >> 6, m = (i & 63) * 4;
        *(float4*)&sA[ll*260 + m] = *(const float4*)&ab[(size_t)ll*256 + m];
    }
    const float* vb = vt + (size_t)bh*6144;
    for (int i = tid; i < 6144; i += 256){
        int m = i / 24, dd = i - m*24;
        sV[dd*260 + m] = vb[i];
    }
    __syncthreads();
    int w = tid >> 5, lane = tid & 31;
    if (lane < 24){
        const float* vr = &sV[lane*260];
#pragma unroll
        for (int j = 0; j < 8; j++){
            int ll = w*8 + j;
            const float* ar = &sA[ll*260];
            float acc = 0.f;
#pragma unroll 8
            for (int m = 0; m < 256; m += 4){
                float4 a = *(const float4*)&ar[m];
                float4 v = *(const float4*)&vr[m];
                acc += a.x*v.x + a.y*v.y + a.z*v.z + a.w*v.w;
            }
            vatt[(size_t)(b*256 + l0 + ll)*768 + lane*32 + h] = acc;
        }
    }
}

// ---------------- host ----------------
extern "C" void kernel_launch(void* const* d_in, const int* in_sizes, int n_in,
                              void* d_out, int out_size)
{
    const float* h_in   = (const float*)d_in[0];
    const float* e_in   = (const float*)d_in[1];
    const float* mask   = (const float*)d_in[2];
    const float* ln_h_g = (const float*)d_in[3];
    const float* ln_h_b = (const float*)d_in[4];
    const float* ln_e_g = (const float*)d_in[5];
    const float* ln_e_b = (const float*)d_in[6];
    const float* W_qkv  = (const float*)d_in[7];
    const float* b_qkv  = (const float*)d_in[8];
    const float* W_eg   = (const float*)d_in[9];
    const float* b_eg   = (const float*)d_in[10];
    const float* W_oh   = (const float*)d_in[11];
    const float* b_oh   = (const float*)d_in[12];
    const float* W_oe   = (const float*)d_in[13];
    const float* b_oe   = (const float*)d_in[14];
    const float* nffn_g = (const float*)d_in[15];
    const float* nffn_b = (const float*)d_in[16];
    const float* nW1    = (const float*)d_in[17];
    const float* nb1    = (const float*)d_in[18];
    const float* nW2    = (const float*)d_in[19];
    const float* nb2    = (const float*)d_in[20];
    const float* effn_g = (const float*)d_in[21];
    const float* effn_b = (const float*)d_in[22];
    const float* eW1    = (const float*)d_in[23];
    const float* eb1    = (const float*)d_in[24];
    const float* eW2    = (const float*)d_in[25];
    const float* eb2    = (const float*)d_in[26];

    float* out_h = (float*)d_out;
    float* out_e = out_h + (size_t)ROWS * DD_;

    float *hln, *qt, *kt, *vt, *qk, *aa, *vatt, *hmid, *hln2, *tbuf;
    cudaGetSymbolAddress((void**)&hln,  g_hln);
    cudaGetSymbolAddress((void**)&qt,   g_qt);
    cudaGetSymbolAddress((void**)&kt,   g_kt);
    cudaGetSymbolAddress((void**)&vt,   g_vt);
    cudaGetSymbolAddress((void**)&qk,   g_qk);
    cudaGetSymbolAddress((void**)&aa,   g_a);
    cudaGetSymbolAddress((void**)&vatt, g_vatt);
    cudaGetSymbolAddress((void**)&hmid, g_hmid);
    cudaGetSymbolAddress((void**)&hln2, g_hln2);
    cudaGetSymbolAddress((void**)&tbuf, g_t);

    cudaFuncSetAttribute(edge_attn_kernel,
                         cudaFuncAttributeMaxDynamicSharedMemorySize,
                         EK_FLOATS * 4);
    cudaFuncSetAttribute(av_kernel,
                         cudaFuncAttributeMaxDynamicSharedMemorySize,
                         AV_FLOATS * 4);

    // 1) h layernorm
    ln768_kernel<<<ROWS, 256>>>(h_in, ln_h_g, ln_h_b, hln);

    // 2) QKV GEMM with transposed scatter
    gemm_qkv<<<dim3(18, 16), 256>>>(hln, W_qkv, b_qkv, qt, kt, vt);

    // 3) QK = Q K^T per head
    qk_kernel<<<dim3(4, 256), 256>>>(qt, kt, qk);

    // 4) fused edge attention + edge FFN -> e_out, A'
    edge_attn_kernel<<<ROWS, 512, EK_FLOATS * 4>>>(
        e_in, mask, qk,
        W_eg, b_eg, W_oe, b_oe,
        ln_e_g, ln_e_b, effn_g, effn_b,
        eW1, eb1, eW2, eb2,
        out_e, aa);

    // 5) V_att = A' @ V
    av_kernel<<<dim3(4, 256), 256, AV_FLOATS * 4>>>(aa, vt, vatt);

    // 6) h_mid = h + V_att @ W_oh + b_oh
    gemm128<0><<<dim3(6, 16), 256>>>(vatt, W_oh, b_oh, h_in, hmid,
                                     ROWS, DD_, DD_);

    // 7) node FFN
    ln768_kernel<<<ROWS, 256>>>(hmid, nffn_g, nffn_b, hln2);
    gemm128<1><<<dim3(6, 16), 256>>>(hln2, nW1, nb1, nullptr, tbuf,
                                     ROWS, DD_, DD_);
    gemm128<0><<<dim3(6, 16), 256>>>(tbuf, nW2, nb2, hmid, out_h,
                                     ROWS, DD_, DD_);
}

// round 5
// speedup vs baseline: 1.5784x; 1.1580x over previous
#include <cuda_runtime.h>
#include <cstddef>

// ---------------- problem constants ----------------
#define BB 8
#define NN 256
#define DD_ 768
#define ROWS (BB*NN)     // 2048
#define SCALE_Q 0.20412414523193154f   // 24^-0.5
#define FULLMASK 0xffffffffu

// ---------------- scratch (device globals; no allocation) ----------------
__device__ float g_hln [ROWS*DD_];
__device__ float g_qt  [8*32*256*24];
__device__ float g_kt  [8*32*256*24];
__device__ float g_vt  [8*32*256*24];
__device__ float g_qk  [8*32*256*256];
__device__ float g_a   [8*32*256*256];
__device__ float g_vatt[ROWS*DD_];
__device__ float g_hmid[ROWS*DD_];
__device__ float g_hln2[ROWS*DD_];
__device__ float g_t   [ROWS*DD_];

// ---------------- helpers ----------------
__device__ __forceinline__ float warpSum(float v){
#pragma unroll
    for (int o = 16; o; o >>= 1) v += __shfl_xor_sync(FULLMASK, v, o);
    return v;
}
__device__ __forceinline__ float warpMax(float v){
#pragma unroll
    for (int o = 16; o; o >>= 1) v = fmaxf(v, __shfl_xor_sync(FULLMASK, v, o));
    return v;
}
__device__ __forceinline__ float sum16(float v){
#pragma unroll
    for (int o = 8; o; o >>= 1) v += __shfl_xor_sync(FULLMASK, v, o);
    return v;
}
__device__ __forceinline__ float gelu_tanh(float x){
    float y = 0.7978845608028654f * (x + 0.044715f * x * x * x);
    y = fminf(fmaxf(y, -30.f), 30.f);
    float t = __expf(2.f * y);
    float th = (t - 1.f) / (t + 1.f);
    return 0.5f * x * (1.f + th);
}
__device__ __forceinline__ float sigmoidf_(float x){
    return 1.f / (1.f + __expf(-x));
}

// ---------------- LayerNorm over 768 ----------------
__global__ __launch_bounds__(256) void ln768_kernel(
    const float* __restrict__ x, const float* __restrict__ g,
    const float* __restrict__ b, float* __restrict__ y)
{
    int row = blockIdx.x;
    int tid = threadIdx.x;
    const float* xr = x + (size_t)row * DD_;
    float*       yr = y + (size_t)row * DD_;
    float v0 = xr[tid], v1 = xr[tid+256], v2 = xr[tid+512];
    __shared__ float red[8];
    float s = warpSum(v0 + v1 + v2);
    if ((tid & 31) == 0) red[tid >> 5] = s;
    __syncthreads();
    float tot = 0.f;
#pragma unroll
    for (int i = 0; i < 8; i++) tot += red[i];
    __syncthreads();
    float mean = tot * (1.f/768.f);
    float d0 = v0-mean, d1 = v1-mean, d2 = v2-mean;
    float q = warpSum(d0*d0 + d1*d1 + d2*d2);
    if ((tid & 31) == 0) red[tid >> 5] = q;
    __syncthreads();
    float vt = 0.f;
#pragma unroll
    for (int i = 0; i < 8; i++) vt += red[i];
    float rstd = rsqrtf(vt * (1.f/768.f) + 1e-5f);
    yr[tid]     = d0*rstd*g[tid]     + b[tid];
    yr[tid+256] = d1*rstd*g[tid+256] + b[tid+256];
    yr[tid+512] = d2*rstd*g[tid+512] + b[tid+512];
}

// ---------------- fp32 GEMM 128x128 tile, 8x8/thread ----------------
template<int EPI>
__global__ __launch_bounds__(256) void gemm128(
    const float* __restrict__ A, const float* __restrict__ Bm,
    const float* __restrict__ bias, const float* __restrict__ R,
    float* __restrict__ C, int M, int N, int K)
{
    __shared__ float sA[16][136];
    __shared__ float sB[16][136];
    int m0 = blockIdx.y * 128;
    int n0 = blockIdx.x * 128;
    int tid = threadIdx.x;
    int ar = tid >> 1, ak = (tid & 1) * 8;
    int bk = tid >> 4, bn = (tid & 15) * 8;
    int ty = tid >> 4, tx = tid & 15;
    float acc[8][8];
#pragma unroll
    for (int i = 0; i < 8; i++)
#pragma unroll
        for (int j = 0; j < 8; j++) acc[i][j] = 0.f;

    for (int k0 = 0; k0 < K; k0 += 16){
        const float* ap = &A[(size_t)(m0+ar)*K + k0 + ak];
        float4 a0 = *(const float4*)ap;
        float4 a1 = *(const float4*)(ap+4);
        sA[ak+0][ar]=a0.x; sA[ak+1][ar]=a0.y; sA[ak+2][ar]=a0.z; sA[ak+3][ar]=a0.w;
        sA[ak+4][ar]=a1.x; sA[ak+5][ar]=a1.y; sA[ak+6][ar]=a1.z; sA[ak+7][ar]=a1.w;
        const float* bp = &Bm[(size_t)(k0+bk)*N + n0 + bn];
        *(float4*)&sB[bk][bn]   = *(const float4*)bp;
        *(float4*)&sB[bk][bn+4] = *(const float4*)(bp+4);
        __syncthreads();
#pragma unroll
        for (int kk = 0; kk < 16; kk++){
            float4 x0 = *(const float4*)&sA[kk][ty*8];
            float4 x1 = *(const float4*)&sA[kk][ty*8+4];
            float4 y0 = *(const float4*)&sB[kk][tx*8];
            float4 y1 = *(const float4*)&sB[kk][tx*8+4];
            float a[8] = {x0.x,x0.y,x0.z,x0.w,x1.x,x1.y,x1.z,x1.w};
            float b[8] = {y0.x,y0.y,y0.z,y0.w,y1.x,y1.y,y1.z,y1.w};
#pragma unroll
            for (int i = 0; i < 8; i++)
#pragma unroll
                for (int j = 0; j < 8; j++) acc[i][j] += a[i]*b[j];
        }
        __syncthreads();
    }
#pragma unroll
    for (int i = 0; i < 8; i++){
        int m = m0 + ty*8 + i;
#pragma unroll
        for (int j = 0; j < 8; j++){
            int n = n0 + tx*8 + j;
            float v = acc[i][j] + bias[n];
            if (EPI == 1) v = gelu_tanh(v);
            if (R) v += R[(size_t)m*N + n];
            C[(size_t)m*N + n] = v;
        }
    }
}

// ---------------- QKV GEMM (128x128) with head-transposed scatter ----------------
__global__ __launch_bounds__(256) void gemm_qkv(
    const float* __restrict__ A, const float* __restrict__ Bm,
    const float* __restrict__ bias,
    float* __restrict__ qt, float* __restrict__ kt, float* __restrict__ vt)
{
    const int N = 2304, K = 768;
    __shared__ float sA[16][136];
    __shared__ float sB[16][136];
    int m0 = blockIdx.y * 128;
    int n0 = blockIdx.x * 128;
    int tid = threadIdx.x;
    int ar = tid >> 1, ak = (tid & 1) * 8;
    int bk = tid >> 4, bn = (tid & 15) * 8;
    int ty = tid >> 4, tx = tid & 15;
    float acc[8][8];
#pragma unroll
    for (int i = 0; i < 8; i++)
#pragma unroll
        for (int j = 0; j < 8; j++) acc[i][j] = 0.f;

    for (int k0 = 0; k0 < K; k0 += 16){
        const float* ap = &A[(size_t)(m0+ar)*K + k0 + ak];
        float4 a0 = *(const float4*)ap;
        float4 a1 = *(const float4*)(ap+4);
        sA[ak+0][ar]=a0.x; sA[ak+1][ar]=a0.y; sA[ak+2][ar]=a0.z; sA[ak+3][ar]=a0.w;
        sA[ak+4][ar]=a1.x; sA[ak+5][ar]=a1.y; sA[ak+6][ar]=a1.z; sA[ak+7][ar]=a1.w;
        const float* bp = &Bm[(size_t)(k0+bk)*N + n0 + bn];
        *(float4*)&sB[bk][bn]   = *(const float4*)bp;
        *(float4*)&sB[bk][bn+4] = *(const float4*)(bp+4);
        __syncthreads();
#pragma unroll
        for (int kk = 0; kk < 16; kk++){
            float4 x0 = *(const float4*)&sA[kk][ty*8];
            float4 x1 = *(const float4*)&sA[kk][ty*8+4];
            float4 y0 = *(const float4*)&sB[kk][tx*8];
            float4 y1 = *(const float4*)&sB[kk][tx*8+4];
            float a[8] = {x0.x,x0.y,x0.z,x0.w,x1.x,x1.y,x1.z,x1.w};
            float b[8] = {y0.x,y0.y,y0.z,y0.w,y1.x,y1.y,y1.z,y1.w};
#pragma unroll
            for (int i = 0; i < 8; i++)
#pragma unroll
                for (int j = 0; j < 8; j++) acc[i][j] += a[i]*b[j];
        }
        __syncthreads();
    }
#pragma unroll
    for (int i = 0; i < 8; i++){
        int m = m0 + ty*8 + i;
        int b = m >> 8, l = m & 255;
#pragma unroll
        for (int j = 0; j < 8; j++){
            int n = n0 + tx*8 + j;
            float v = acc[i][j] + bias[n];
            int seg = n / 768;
            int nn = n - seg*768;
            int dd = nn >> 5, h = nn & 31;
            size_t idx = (((size_t)(b*32 + h))*256 + l)*24 + dd;
            if (seg == 0)      qt[idx] = v * SCALE_Q;
            else if (seg == 1) kt[idx] = v;
            else               vt[idx] = v;
        }
    }
}

// ---------------- QK kernel ----------------
__global__ __launch_bounds__(256) void qk_kernel(
    const float* __restrict__ qt, const float* __restrict__ kt,
    float* __restrict__ qk)
{
    int bh = blockIdx.y;
    int l0 = (blockIdx.x >> 1) * 128;
    int m0 = (blockIdx.x & 1) * 128;
    __shared__ float sQ[24*132];
    __shared__ float sK[24*132];
    int tid = threadIdx.x;
    const float* qb = qt + (size_t)bh*6144 + (size_t)l0*24;
    const float* kb = kt + (size_t)bh*6144 + (size_t)m0*24;
    for (int i = tid; i < 3072; i += 256){
        int r = i / 24, d = i - r*24;
        sQ[d*132 + r] = qb[i];
        sK[d*132 + r] = kb[i];
    }
    __syncthreads();
    int tx = tid & 15, ty = tid >> 4;
    float acc[8][8];
#pragma unroll
    for (int i = 0; i < 8; i++)
#pragma unroll
        for (int j = 0; j < 8; j++) acc[i][j] = 0.f;
#pragma unroll 6
    for (int k = 0; k < 24; k++){
        float4 a0 = *(const float4*)&sQ[k*132 + ty*8];
        float4 a1 = *(const float4*)&sQ[k*132 + ty*8 + 4];
        float4 b0 = *(const float4*)&sK[k*132 + tx*8];
        float4 b1 = *(const float4*)&sK[k*132 + tx*8 + 4];
        float a[8] = {a0.x,a0.y,a0.z,a0.w,a1.x,a1.y,a1.z,a1.w};
        float b[8] = {b0.x,b0.y,b0.z,b0.w,b1.x,b1.y,b1.z,b1.w};
#pragma unroll
        for (int i = 0; i < 8; i++)
#pragma unroll
            for (int j = 0; j < 8; j++) acc[i][j] += a[i]*b[j];
    }
    float* out = qk + (size_t)bh*65536 + (size_t)l0*256 + m0;
#pragma unroll
    for (int i = 0; i < 8; i++){
        float* orow = out + (size_t)(ty*8 + i)*256 + tx*8;
        *(float4*)orow     = make_float4(acc[i][0],acc[i][1],acc[i][2],acc[i][3]);
        *(float4*)(orow+4) = make_float4(acc[i][4],acc[i][5],acc[i][6],acc[i][7]);
    }
}

// ---------------- fused edge kernel: one CTA per (b,l), 512 threads ----------------
// 2 groups of 256 threads; each group owns a 128-edge tile. 8x4 thread tile.
// Residual r lives in registers. X buffer swizzled: col = (m + 4*tx_of_k) & 127.
#define OFF_WEG  0
#define OFF_WOE  4096
#define OFF_EW1  6144
#define OFF_EW2  10240
#define OFF_PAR  14336
#define OFF_HHAT 14848          // [32][260]
#define OFF_GATE 23168          // [32][260]
#define OFF_MASK 31488          // [256]
#define OFF_GRP  31744
#define GRP_SZ   12672          // sX [64][132]=8448 + sQKc [32][132]=4224
#define EK_FLOATS (OFF_GRP + 2*GRP_SZ)   // 57088 floats = 228352 B
__global__ __launch_bounds__(512, 1) void edge_attn_kernel(
    const float* __restrict__ e_in, const float* __restrict__ mask,
    const float* __restrict__ qk,
    const float* __restrict__ W_eg, const float* __restrict__ b_eg,
    const float* __restrict__ W_oe, const float* __restrict__ b_oe,
    const float* __restrict__ eln_g, const float* __restrict__ eln_b,
    const float* __restrict__ ffn_g, const float* __restrict__ ffn_b,
    const float* __restrict__ eW1, const float* __restrict__ eb1,
    const float* __restrict__ eW2, const float* __restrict__ eb2,
    float* __restrict__ e_out, float* __restrict__ a_all)
{
    extern __shared__ float sm[];
    float* sWeg  = sm + OFF_WEG;
    float* sWoe  = sm + OFF_WOE;
    float* sEW1  = sm + OFF_EW1;
    float* sEW2  = sm + OFF_EW2;
    float* sPar  = sm + OFF_PAR;
    float* sHhat = sm + OFF_HHAT;
    float* sGate = sm + OFF_GATE;
    float* sMask = sm + OFF_MASK;

    int tid  = threadIdx.x;
    int grp  = tid >> 8;
    int t    = tid & 255;
    int ty   = t >> 4;         // 0..15 -> rows ty*8..+7
    int tx   = t & 15;         // 0..15 -> cols tx*4..+3
    int lane = tid & 31;
    int w    = tid >> 5;
    int row  = blockIdx.x;
    int b    = row >> 8;
    int l    = row & 255;
    int m0g  = grp * 128;
    float* sX   = sm + OFF_GRP + grp*GRP_SZ;   // [64][132] swizzled
    float* sQKc = sX + 8448;                   // [32][132]
    size_t qkbase = ((size_t)b*32)*65536 + (size_t)l*256;

    // ---- stage weights, params, qk chunk, mask ----
    for (int i = tid; i < 4096; i += 512){
        sWeg[i] = W_eg[i]; sEW1[i] = eW1[i]; sEW2[i] = eW2[i];
    }
    for (int i = tid; i < 2048; i += 512) sWoe[i] = W_oe[i];
    if (tid < 64){
        sPar[tid]     = b_eg[tid];
        sPar[64+tid]  = b_oe[tid];
        sPar[128+tid] = eb1[tid];
        sPar[192+tid] = eb2[tid];
        sPar[256+tid] = eln_g[tid];
        sPar[320+tid] = eln_b[tid];
        sPar[384+tid] = ffn_g[tid];
        sPar[448+tid] = ffn_b[tid];
    }
    for (int i = t; i < 1024; i += 256){
        int h = i >> 5, mq = (i & 31) * 4;
        *(float4*)&sQKc[h*132 + mq] =
            *(const float4*)&qk[qkbase + (size_t)h*65536 + m0g + mq];
    }
    if (t < 128) sMask[m0g + t] = mask[(size_t)row*256 + m0g + t];
    __syncthreads();

    float lgv[4], lbv[4], fgv[4], fbv[4];
#pragma unroll
    for (int j = 0; j < 4; j++){
        lgv[j] = sPar[256 + tx*4 + j];
        lbv[j] = sPar[320 + tx*4 + j];
        fgv[j] = sPar[384 + tx*4 + j];
        fbv[j] = sPar[448 + tx*4 + j];
    }

    float r_[8][4];   // residual in registers

    // ---- LN1: gmem -> regs -> swizzled sX ----
#pragma unroll
    for (int i = 0; i < 8; i++){
        float4 e4 = *(const float4*)&e_in[((size_t)row*256 + m0g + ty*8 + i)*64 + tx*4];
        r_[i][0]=e4.x; r_[i][1]=e4.y; r_[i][2]=e4.z; r_[i][3]=e4.w;
        float s = sum16(e4.x + e4.y + e4.z + e4.w);
        float mean = s * (1.f/64.f);
        float d0=e4.x-mean, d1=e4.y-mean, d2=e4.z-mean, d3=e4.w-mean;
        float q = sum16(d0*d0 + d1*d1 + d2*d2 + d3*d3);
        float rs = rsqrtf(q * (1.f/64.f) + 1e-5f);
        int col = (ty*8 + i + tx*4) & 127;
        sX[(tx*4+0)*132 + col] = d0*rs*lgv[0] + lbv[0];
        sX[(tx*4+1)*132 + col] = d1*rs*lgv[1] + lbv[1];
        sX[(tx*4+2)*132 + col] = d2*rs*lgv[2] + lbv[2];
        sX[(tx*4+3)*132 + col] = d3*rs*lgv[3] + lbv[3];
    }
    __syncthreads();

    float acc[8][4];
    // ---- GEMM1: EG = X @ W_eg ----
#pragma unroll
    for (int i=0;i<8;i++)
#pragma unroll
        for (int j=0;j<4;j++) acc[i][j]=0.f;
#pragma unroll 8
    for (int k = 0; k < 64; k++){
        int ofs = k & ~3;
        float4 a0 = *(const float4*)&sX[k*132 + ((ty*8     + ofs) & 127)];
        float4 a1 = *(const float4*)&sX[k*132 + ((ty*8 + 4 + ofs) & 127)];
        float4 b4 = *(const float4*)&sWeg[k*64 + tx*4];
        float a[8]={a0.x,a0.y,a0.z,a0.w,a1.x,a1.y,a1.z,a1.w};
        float bv[4]={b4.x,b4.y,b4.z,b4.w};
#pragma unroll
        for (int i=0;i<8;i++)
#pragma unroll
            for (int j=0;j<4;j++) acc[i][j] += a[i]*bv[j];
    }
    if (tx < 8){
#pragma unroll
        for (int j=0;j<4;j++){
            int h = tx*4 + j;
            float bb = sPar[h];
#pragma unroll
            for (int i=0;i<8;i++){
                int m = ty*8 + i;
                sHhat[h*260 + m0g + m] = acc[i][j] + bb + sQKc[h*132 + m];
            }
        }
    } else {
#pragma unroll
        for (int j=0;j<4;j++){
            int n = tx*4 + j;
            int h = n - 32;
            float bb = sPar[n];
#pragma unroll
            for (int i=0;i<8;i++){
                int m = ty*8 + i;
                sGate[h*260 + m0g + m] = sigmoidf_(acc[i][j] + bb + sMask[m0g + m]);
            }
        }
    }
    __syncthreads();

    // ---- GEMM2: e_att = H_hat @ W_oe ; r = e + e_att + b_oe ----
#pragma unroll
    for (int i=0;i<8;i++)
#pragma unroll
        for (int j=0;j<4;j++) acc[i][j]=0.f;
#pragma unroll 8
    for (int k = 0; k < 32; k++){
        float4 a0 = *(const float4*)&sHhat[k*260 + m0g + ty*8];
        float4 a1 = *(const float4*)&sHhat[k*260 + m0g + ty*8 + 4];
        float4 b4 = *(const float4*)&sWoe[k*64 + tx*4];
        float a[8]={a0.x,a0.y,a0.z,a0.w,a1.x,a1.y,a1.z,a1.w};
        float bv[4]={b4.x,b4.y,b4.z,b4.w};
#pragma unroll
        for (int i=0;i<8;i++)
#pragma unroll
            for (int j=0;j<4;j++) acc[i][j] += a[i]*bv[j];
    }
#pragma unroll
    for (int i=0;i<8;i++)
#pragma unroll
        for (int j=0;j<4;j++)
            r_[i][j] += acc[i][j] + sPar[64 + tx*4 + j];

    // ---- LN2 on r (regs) -> swizzled sX ----
#pragma unroll
    for (int i = 0; i < 8; i++){
        float s = sum16(r_[i][0] + r_[i][1] + r_[i][2] + r_[i][3]);
        float mean = s * (1.f/64.f);
        float d0=r_[i][0]-mean, d1=r_[i][1]-mean, d2=r_[i][2]-mean, d3=r_[i][3]-mean;
        float q = sum16(d0*d0 + d1*d1 + d2*d2 + d3*d3);
        float rs = rsqrtf(q * (1.f/64.f) + 1e-5f);
        int col = (ty*8 + i + tx*4) & 127;
        sX[(tx*4+0)*132 + col] = d0*rs*fgv[0] + fbv[0];
        sX[(tx*4+1)*132 + col] = d1*rs*fgv[1] + fbv[1];
        sX[(tx*4+2)*132 + col] = d2*rs*fgv[2] + fbv[2];
        sX[(tx*4+3)*132 + col] = d3*rs*fgv[3] + fbv[3];
    }
    __syncthreads();

    // ---- GEMM3: T = gelu(X2 @ eW1 + b1) ----
#pragma unroll
    for (int i=0;i<8;i++)
#pragma unroll
        for (int j=0;j<4;j++) acc[i][j]=0.f;
#pragma unroll 8
    for (int k = 0; k < 64; k++){
        int ofs = k & ~3;
        float4 a0 = *(const float4*)&sX[k*132 + ((ty*8     + ofs) & 127)];
        float4 a1 = *(const float4*)&sX[k*132 + ((ty*8 + 4 + ofs) & 127)];
        float4 b4 = *(const float4*)&sEW1[k*64 + tx*4];
        float a[8]={a0.x,a0.y,a0.z,a0.w,a1.x,a1.y,a1.z,a1.w};
        float bv[4]={b4.x,b4.y,b4.z,b4.w};
#pragma unroll
        for (int i=0;i<8;i++)
#pragma unroll
            for (int j=0;j<4;j++) acc[i][j] += a[i]*bv[j];
    }
    __syncthreads();   // all reads of sX done
#pragma unroll
    for (int i = 0; i < 8; i++){
        int col = (ty*8 + i + tx*4) & 127;
#pragma unroll
        for (int j = 0; j < 4; j++)
            sX[(tx*4+j)*132 + col] = gelu_tanh(acc[i][j] + sPar[128 + tx*4 + j]);
    }
    __syncthreads();

    // ---- GEMM4: O = T @ eW2 + b2 ; e_out = r + O ----
#pragma unroll
    for (int i=0;i<8;i++)
#pragma unroll
        for (int j=0;j<4;j++) acc[i][j]=0.f;
#pragma unroll 8
    for (int k = 0; k < 64; k++){
        int ofs = k & ~3;
        float4 a0 = *(const float4*)&sX[k*132 + ((ty*8     + ofs) & 127)];
        float4 a1 = *(const float4*)&sX[k*132 + ((ty*8 + 4 + ofs) & 127)];
        float4 b4 = *(const float4*)&sEW2[k*64 + tx*4];
        float a[8]={a0.x,a0.y,a0.z,a0.w,a1.x,a1.y,a1.z,a1.w};
        float bv[4]={b4.x,b4.y,b4.z,b4.w};
#pragma unroll
        for (int i=0;i<8;i++)
#pragma unroll
            for (int j=0;j<4;j++) acc[i][j] += a[i]*bv[j];
    }
#pragma unroll
    for (int i = 0; i < 8; i++){
        float4 o;
        o.x = r_[i][0] + acc[i][0] + sPar[192 + tx*4 + 0];
        o.y = r_[i][1] + acc[i][1] + sPar[192 + tx*4 + 1];
        o.z = r_[i][2] + acc[i][2] + sPar[192 + tx*4 + 2];
        o.w = r_[i][3] + acc[i][3] + sPar[192 + tx*4 + 3];
        *(float4*)&e_out[((size_t)row*256 + m0g + ty*8 + i)*64 + tx*4] = o;
    }
    __syncthreads();

    // ---- softmax over m per head, fold gates & degree ----
#pragma unroll
    for (int hi = 0; hi < 2; hi++){
        int h = w + hi*16;
        float p[8], g[8];
        float mx = -3.4e38f;
#pragma unroll
        for (int j = 0; j < 8; j++){
            int m = j*32 + lane;
            p[j] = sHhat[h*260 + m] + sMask[m];
            mx = fmaxf(mx, p[j]);
        }
        mx = warpMax(mx);
        float s = 0.f, gs = 0.f;
#pragma unroll
        for (int j = 0; j < 8; j++){
            p[j] = __expf(p[j] - mx);
            s += p[j];
            g[j] = sGate[h*260 + j*32 + lane];
            gs += g[j];
        }
        s = warpSum(s); gs = warpSum(gs);
        float c = (1.f / s) * log1pf(gs);
        float* ao = a_all + (((size_t)(b*32 + h))*256 + l)*256;
#pragma unroll
        for (int j = 0; j < 8; j++)
            ao[j*32 + lane] = p[j] * g[j] * c;
    }
}

// ---------------- AV kernel ----------------
#define AV_FLOATS (64*260 + 24*260)
__global__ __launch_bounds__(256) void av_kernel(
    const float* __restrict__ a_all, const float* __restrict__ vt,
    float* __restrict__ vatt)
{
    extern __shared__ float sm[];
    float* sA = sm;
    float* sV = sm + 64*260;
    int bh = blockIdx.y;
    int l0 = blockIdx.x * 64;
    int b = bh >> 5, h = bh & 31;
    int tid = threadIdx.x;
    const float* ab = a_all + (size_t)bh*65536 + (size_t)l0*256;
    for (int i = tid; i < 4096; i += 256){
        int ll = i >> 6, m = (i & 63) * 4;
        *(float4*)&sA[ll*260 + m] = *(const float4*)&ab[(size_t)ll*256 + m];
    }
    const float* vb = vt + (size_t)bh*6144;
    for (int i = tid; i < 6144; i += 256){
        int m = i / 24, dd = i - m*24;
        sV[dd*260 + m] = vb[i];
    }
    __syncthreads();
    int w = tid >> 5, lane = tid & 31;
    if (lane < 24){
        const float* vr = &sV[lane*260];
#pragma unroll
        for (int j = 0; j < 8; j++){
            int ll = w*8 + j;
            const float* ar = &sA[ll*260];
            float acc = 0.f;
#pragma unroll 8
            for (int m = 0; m < 256; m += 4){
                float4 a = *(const float4*)&ar[m];
                float4 v = *(const float4*)&vr[m];
                acc += a.x*v.x + a.y*v.y + a.z*v.z + a.w*v.w;
            }
            vatt[(size_t)(b*256 + l0 + ll)*768 + lane*32 + h] = acc;
        }
    }
}

// ---------------- host ----------------
extern "C" void kernel_launch(void* const* d_in, const int* in_sizes, int n_in,
                              void* d_out, int out_size)
{
    const float* h_in   = (const float*)d_in[0];
    const float* e_in   = (const float*)d_in[1];
    const float* mask   = (const float*)d_in[2];
    const float* ln_h_g = (const float*)d_in[3];
    const float* ln_h_b = (const float*)d_in[4];
    const float* ln_e_g = (const float*)d_in[5];
    const float* ln_e_b = (const float*)d_in[6];
    const float* W_qkv  = (const float*)d_in[7];
    const float* b_qkv  = (const float*)d_in[8];
    const float* W_eg   = (const float*)d_in[9];
    const float* b_eg   = (const float*)d_in[10];
    const float* W_oh   = (const float*)d_in[11];
    const float* b_oh   = (const float*)d_in[12];
    const float* W_oe   = (const float*)d_in[13];
    const float* b_oe   = (const float*)d_in[14];
    const float* nffn_g = (const float*)d_in[15];
    const float* nffn_b = (const float*)d_in[16];
    const float* nW1    = (const float*)d_in[17];
    const float* nb1    = (const float*)d_in[18];
    const float* nW2    = (const float*)d_in[19];
    const float* nb2    = (const float*)d_in[20];
    const float* effn_g = (const float*)d_in[21];
    const float* effn_b = (const float*)d_in[22];
    const float* eW1    = (const float*)d_in[23];
    const float* eb1    = (const float*)d_in[24];
    const float* eW2    = (const float*)d_in[25];
    const float* eb2    = (const float*)d_in[26];

    float* out_h = (float*)d_out;
    float* out_e = out_h + (size_t)ROWS * DD_;

    float *hln, *qt, *kt, *vt, *qk, *aa, *vatt, *hmid, *hln2, *tbuf;
    cudaGetSymbolAddress((void**)&hln,  g_hln);
    cudaGetSymbolAddress((void**)&qt,   g_qt);
    cudaGetSymbolAddress((void**)&kt,   g_kt);
    cudaGetSymbolAddress((void**)&vt,   g_vt);
    cudaGetSymbolAddress((void**)&qk,   g_qk);
    cudaGetSymbolAddress((void**)&aa,   g_a);
    cudaGetSymbolAddress((void**)&vatt, g_vatt);
    cudaGetSymbolAddress((void**)&hmid, g_hmid);
    cudaGetSymbolAddress((void**)&hln2, g_hln2);
    cudaGetSymbolAddress((void**)&tbuf, g_t);

    cudaFuncSetAttribute(edge_attn_kernel,
                         cudaFuncAttributeMaxDynamicSharedMemorySize,
                         EK_FLOATS * 4);
    cudaFuncSetAttribute(av_kernel,
                         cudaFuncAttributeMaxDynamicSharedMemorySize,
                         AV_FLOATS * 4);

    // 1) h layernorm
    ln768_kernel<<<ROWS, 256>>>(h_in, ln_h_g, ln_h_b, hln);

    // 2) QKV GEMM with transposed scatter
    gemm_qkv<<<dim3(18, 16), 256>>>(hln, W_qkv, b_qkv, qt, kt, vt);

    // 3) QK = Q K^T per head
    qk_kernel<<<dim3(4, 256), 256>>>(qt, kt, qk);

    // 4) fused edge attention + edge FFN -> e_out, A'
    edge_attn_kernel<<<ROWS, 512, EK_FLOATS * 4>>>(
        e_in, mask, qk,
        W_eg, b_eg, W_oe, b_oe,
        ln_e_g, ln_e_b, effn_g, effn_b,
        eW1, eb1, eW2, eb2,
        out_e, aa);

    // 5) V_att = A' @ V
    av_kernel<<<dim3(4, 256), 256, AV_FLOATS * 4>>>(aa, vt, vatt);

    // 6) h_mid = h + V_att @ W_oh + b_oh
    gemm128<0><<<dim3(6, 16), 256>>>(vatt, W_oh, b_oh, h_in, hmid,
                                     ROWS, DD_, DD_);

    // 7) node FFN
    ln768_kernel<<<ROWS, 256>>>(hmid, nffn_g, nffn_b, hln2);
    gemm128<1><<<dim3(6, 16), 256>>>(hln2, nW1, nb1, nullptr, tbuf,
                                     ROWS, DD_, DD_);
    gemm128<0><<<dim3(6, 16), 256>>>(tbuf, nW2, nb2, hmid, out_h,
                                     ROWS, DD_, DD_);
}